// round 4
// baseline (speedup 1.0000x reference)
#include <cuda_runtime.h>
#include <cuda_bf16.h>
#include <math.h>

// Problem constants
#define BB 4
#define SS 2048
#define DD 1024
#define HH 16
#define HD 64
#define FF 4096
#define ROWS (BB*SS)          // 8192

// ---------------- scratch (device globals; no allocation) ----------------
__device__ float g_ln  [(size_t)ROWS * DD];
__device__ float g_q   [(size_t)ROWS * DD];
__device__ float g_k   [(size_t)ROWS * DD];
__device__ float g_v   [(size_t)ROWS * DD];
__device__ float g_att [(size_t)ROWS * DD];
__device__ float g_x1  [(size_t)ROWS * DD];
__device__ float g_h   [(size_t)ROWS * FF];

// ---------------- LayerNorm: one block per row, D=1024 ----------------
__global__ void ln_kernel(const float* __restrict__ x,
                          const float* __restrict__ g,
                          const float* __restrict__ b,
                          float* __restrict__ out)
{
    const int row = blockIdx.x;
    const float* xr = x + (size_t)row * DD;
    float* orow = out + (size_t)row * DD;

    float s = 0.f, s2 = 0.f;
    for (int i = threadIdx.x; i < DD; i += blockDim.x) {
        float v = xr[i];
        s += v; s2 += v * v;
    }
    __shared__ float red[64];
    for (int o = 16; o; o >>= 1) {
        s  += __shfl_xor_sync(0xffffffffu, s,  o);
        s2 += __shfl_xor_sync(0xffffffffu, s2, o);
    }
    int wid = threadIdx.x >> 5, lid = threadIdx.x & 31;
    if (lid == 0) { red[wid] = s; red[wid + 32] = s2; }
    __syncthreads();
    if (wid == 0) {
        int nw = blockDim.x >> 5;
        s  = (lid < nw) ? red[lid] : 0.f;
        s2 = (lid < nw) ? red[lid + 32] : 0.f;
        for (int o = 16; o; o >>= 1) {
            s  += __shfl_xor_sync(0xffffffffu, s,  o);
            s2 += __shfl_xor_sync(0xffffffffu, s2, o);
        }
        if (lid == 0) { red[0] = s; red[1] = s2; }
    }
    __syncthreads();
    float mean = red[0] * (1.0f / DD);
    float var  = red[1] * (1.0f / DD) - mean * mean;
    float inv  = rsqrtf(var + 1e-5f);
    for (int i = threadIdx.x; i < DD; i += blockDim.x)
        orow[i] = (xr[i] - mean) * inv * g[i] + b[i];
}

// ---------------- SGEMM: C[M,N] = A[M,K] @ B[K,N] (+bias,+gelu,+resid) ---
// Tiles: 128x128x16, 256 threads, 8x8 per thread. All dims divisible.
__global__ void __launch_bounds__(256, 2)
sgemm_kernel(const float* __restrict__ A, const float* __restrict__ B,
             const float* __restrict__ bias, const float* __restrict__ resid,
             float* __restrict__ C, int M, int N, int K, int dogelu)
{
    const int BM = 128, BN = 128, BK = 16;
    __shared__ float As[16][BM + 4];
    __shared__ float Bs[16][BN];

    const int tid = threadIdx.x;
    const int tx = tid & 15, ty = tid >> 4;
    const int bm = blockIdx.y * BM, bn = blockIdx.x * BN;

    float acc[8][8];
    #pragma unroll
    for (int i = 0; i < 8; i++)
        #pragma unroll
        for (int j = 0; j < 8; j++) acc[i][j] = 0.f;

    const float* Ab = A + (size_t)bm * K;
    const float* Bb = B + bn;

    const int a_r0 = tid >> 2;          // 0..63
    const int a_c  = (tid & 3) * 4;     // 0,4,8,12
    const int b_r0 = tid >> 5;          // 0..7
    const int b_c  = (tid & 31) * 4;    // 0..124

    for (int k0 = 0; k0 < K; k0 += BK) {
        #pragma unroll
        for (int u = 0; u < 2; u++) {
            int r = a_r0 + u * 64;
            float4 va = *(const float4*)(Ab + (size_t)r * K + k0 + a_c);
            As[a_c + 0][r] = va.x; As[a_c + 1][r] = va.y;
            As[a_c + 2][r] = va.z; As[a_c + 3][r] = va.w;
        }
        #pragma unroll
        for (int u = 0; u < 2; u++) {
            int r = b_r0 + u * 8;
            *(float4*)(&Bs[r][b_c]) = *(const float4*)(Bb + (size_t)(k0 + r) * N + b_c);
        }
        __syncthreads();
        #pragma unroll
        for (int k = 0; k < BK; k++) {
            float a[8], bb[8];
            *(float4*)(a)      = *(const float4*)(&As[k][ty * 8]);
            *(float4*)(a + 4)  = *(const float4*)(&As[k][ty * 8 + 4]);
            *(float4*)(bb)     = *(const float4*)(&Bs[k][tx * 8]);
            *(float4*)(bb + 4) = *(const float4*)(&Bs[k][tx * 8 + 4]);
            #pragma unroll
            for (int i = 0; i < 8; i++)
                #pragma unroll
                for (int j = 0; j < 8; j++)
                    acc[i][j] += a[i] * bb[j];
        }
        __syncthreads();
    }

    #pragma unroll
    for (int i = 0; i < 8; i++) {
        int row = bm + ty * 8 + i;
        #pragma unroll
        for (int j4 = 0; j4 < 2; j4++) {
            int col = bn + tx * 8 + j4 * 4;
            float4 r;
            r.x = acc[i][j4*4+0]; r.y = acc[i][j4*4+1];
            r.z = acc[i][j4*4+2]; r.w = acc[i][j4*4+3];
            if (bias) {
                float4 bv = *(const float4*)(bias + col);
                r.x += bv.x; r.y += bv.y; r.z += bv.z; r.w += bv.w;
            }
            if (dogelu) {
                r.x = 0.5f * r.x * (1.0f + erff(r.x * 0.70710678118654752f));
                r.y = 0.5f * r.y * (1.0f + erff(r.y * 0.70710678118654752f));
                r.z = 0.5f * r.z * (1.0f + erff(r.z * 0.70710678118654752f));
                r.w = 0.5f * r.w * (1.0f + erff(r.w * 0.70710678118654752f));
            }
            if (resid) {
                float4 rv = *(const float4*)(resid + (size_t)row * N + col);
                r.x += rv.x; r.y += rv.y; r.z += rv.z; r.w += rv.w;
            }
            *(float4*)(C + (size_t)row * N + col) = r;
        }
    }
}

// ---------------- Flash attention (fp32, online softmax) ----------------
// grid = (S/128, H, B), 128 threads; each thread owns one query row.
// mask is int32 (bool promoted by the harness): nonzero = attend.
__global__ void __launch_bounds__(128, 2)
flash_kernel(const float* __restrict__ Q, const float* __restrict__ K,
             const float* __restrict__ V, const int* __restrict__ mask,
             float* __restrict__ O)
{
    const int BKV = 32;
    __shared__ float Ks[BKV][HD];
    __shared__ float Vs[BKV][HD];

    const int b = blockIdx.z, h = blockIdx.y;
    const int tid = threadIdx.x;
    const int qi = blockIdx.x * 128 + tid;

    const float* qp = Q + ((size_t)(b * SS + qi)) * DD + h * HD;
    float q[HD];
    #pragma unroll
    for (int i = 0; i < 16; i++)
        *(float4*)(q + 4 * i) = *(const float4*)(qp + 4 * i);

    float acc[HD];
    #pragma unroll
    for (int d = 0; d < HD; d++) acc[d] = 0.f;
    float m = -INFINITY, l = 0.f;
    int any = 0;

    const int* mrow = mask + ((size_t)(b * SS + qi)) * SS;

    for (int t0 = 0; t0 < SS; t0 += BKV) {
        #pragma unroll
        for (int u = 0; u < 4; u++) {
            int f = tid + u * 128;
            int r = f >> 4, c = (f & 15) * 4;
            size_t base = ((size_t)(b * SS + t0 + r)) * DD + h * HD + c;
            *(float4*)(&Ks[r][c]) = *(const float4*)(K + base);
            *(float4*)(&Vs[r][c]) = *(const float4*)(V + base);
        }
        __syncthreads();

        float s[BKV];
        float tmax = -INFINITY;
        #pragma unroll
        for (int kk = 0; kk < BKV; kk++) {
            float dot = 0.f;
            #pragma unroll
            for (int d4 = 0; d4 < 16; d4++) {
                float4 kv = *(const float4*)(&Ks[kk][d4 * 4]);
                dot += q[d4*4+0] * kv.x + q[d4*4+1] * kv.y
                     + q[d4*4+2] * kv.z + q[d4*4+3] * kv.w;
            }
            dot *= 0.125f;
            int mb = mrow[t0 + kk];
            any |= mb;
            s[kk] = mb ? dot : -1e30f;
            tmax = fmaxf(tmax, s[kk]);
        }

        float mnew = fmaxf(m, tmax);
        float corr = __expf(m - mnew);     // exp(-inf)=0 on first tile
        l *= corr;
        #pragma unroll
        for (int d = 0; d < HD; d++) acc[d] *= corr;

        #pragma unroll
        for (int kk = 0; kk < BKV; kk++) {
            float p = __expf(s[kk] - mnew);
            l += p;
            #pragma unroll
            for (int d4 = 0; d4 < 16; d4++) {
                float4 vv = *(const float4*)(&Vs[kk][d4 * 4]);
                acc[d4*4+0] += p * vv.x; acc[d4*4+1] += p * vv.y;
                acc[d4*4+2] += p * vv.z; acc[d4*4+3] += p * vv.w;
            }
        }
        m = mnew;
        __syncthreads();
    }

    float invl = (any && l > 0.f) ? (1.0f / l) : 0.0f;  // wipe_attn: all-masked -> 0
    float* op = O + ((size_t)(b * SS + qi)) * DD + h * HD;
    #pragma unroll
    for (int d4 = 0; d4 < 16; d4++) {
        float4 o;
        o.x = acc[d4*4+0] * invl; o.y = acc[d4*4+1] * invl;
        o.z = acc[d4*4+2] * invl; o.w = acc[d4*4+3] * invl;
        *(float4*)(op + d4 * 4) = o;
    }
}

// ---------------- launch ----------------
extern "C" void kernel_launch(void* const* d_in, const int* in_sizes, int n_in,
                              void* d_out, int out_size)
{
    const float* x      = (const float*)d_in[0];
    const int*   mask   = (const int*)d_in[1];
    const float* ln1_g  = (const float*)d_in[2];
    const float* ln1_b  = (const float*)d_in[3];
    const float* wq     = (const float*)d_in[4];
    const float* wk     = (const float*)d_in[5];
    const float* wv     = (const float*)d_in[6];
    const float* wo     = (const float*)d_in[7];
    const float* bo     = (const float*)d_in[8];
    const float* ln2_g  = (const float*)d_in[9];
    const float* ln2_b  = (const float*)d_in[10];
    const float* w1     = (const float*)d_in[11];
    const float* b1     = (const float*)d_in[12];
    const float* w2     = (const float*)d_in[13];
    const float* b2     = (const float*)d_in[14];
    float* out = (float*)d_out;

    float *ln, *q, *k, *v, *att, *x1, *hbuf;
    cudaGetSymbolAddress((void**)&ln,   g_ln);
    cudaGetSymbolAddress((void**)&q,    g_q);
    cudaGetSymbolAddress((void**)&k,    g_k);
    cudaGetSymbolAddress((void**)&v,    g_v);
    cudaGetSymbolAddress((void**)&att,  g_att);
    cudaGetSymbolAddress((void**)&x1,   g_x1);
    cudaGetSymbolAddress((void**)&hbuf, g_h);

    // 1) LN1
    ln_kernel<<<ROWS, 256>>>(x, ln1_g, ln1_b, ln);

    // 2) Q,K,V projections
    dim3 gQKV(DD / 128, ROWS / 128);
    sgemm_kernel<<<gQKV, 256>>>(ln, wq, nullptr, nullptr, q, ROWS, DD, DD, 0);
    sgemm_kernel<<<gQKV, 256>>>(ln, wk, nullptr, nullptr, k, ROWS, DD, DD, 0);
    sgemm_kernel<<<gQKV, 256>>>(ln, wv, nullptr, nullptr, v, ROWS, DD, DD, 0);

    // 3) attention
    dim3 gF(SS / 128, HH, BB);
    flash_kernel<<<gF, 128>>>(q, k, v, mask, att);

    // 4) output projection + residual
    sgemm_kernel<<<gQKV, 256>>>(att, wo, bo, x, x1, ROWS, DD, DD, 0);

    // 5) LN2
    ln_kernel<<<ROWS, 256>>>(x1, ln2_g, ln2_b, ln);

    // 6) MLP up + erf gelu
    dim3 gM1(FF / 128, ROWS / 128);
    sgemm_kernel<<<gM1, 256>>>(ln, w1, b1, nullptr, hbuf, ROWS, FF, DD, 1);

    // 7) MLP down + residual -> out
    dim3 gM2(DD / 128, ROWS / 128);
    sgemm_kernel<<<gM2, 256>>>(hbuf, w2, b2, x1, out, ROWS, DD, FF, 0);
}

// round 7
// speedup vs baseline: 1.3040x; 1.3040x over previous
#include <cuda_runtime.h>
#include <cuda_bf16.h>
#include <math.h>
#include <stdint.h>

// Problem constants
#define BB 4
#define SS 2048
#define DD 1024
#define HH 16
#define HD 64
#define FF 4096
#define ROWS (BB*SS)          // 8192

// ---------------- scratch (device globals; no allocation) ----------------
__device__ __nv_bfloat16 g_lnh[(size_t)ROWS * DD];
__device__ __nv_bfloat16 g_lnl[(size_t)ROWS * DD];
__device__ float g_q [(size_t)ROWS * DD];
__device__ float g_k [(size_t)ROWS * DD];
__device__ float g_v [(size_t)ROWS * DD];
__device__ __nv_bfloat16 g_atth[(size_t)ROWS * DD];
__device__ __nv_bfloat16 g_attl[(size_t)ROWS * DD];
__device__ float g_x1[(size_t)ROWS * DD];
__device__ __nv_bfloat16 g_hh[(size_t)ROWS * FF];
__device__ __nv_bfloat16 g_hl[(size_t)ROWS * FF];
// transposed + split weights: wt[N][K]
__device__ __nv_bfloat16 g_wqh[(size_t)DD*DD], g_wql[(size_t)DD*DD];
__device__ __nv_bfloat16 g_wkh[(size_t)DD*DD], g_wkl[(size_t)DD*DD];
__device__ __nv_bfloat16 g_wvh[(size_t)DD*DD], g_wvl[(size_t)DD*DD];
__device__ __nv_bfloat16 g_woh[(size_t)DD*DD], g_wol[(size_t)DD*DD];
__device__ __nv_bfloat16 g_w1h[(size_t)DD*FF], g_w1l[(size_t)DD*FF];
__device__ __nv_bfloat16 g_w2h[(size_t)FF*DD], g_w2l[(size_t)FF*DD];

// ---------------- helpers ----------------
__device__ __forceinline__ uint32_t smem_u32(const void* p) {
    uint32_t a;
    asm("{ .reg .u64 t; cvta.to.shared.u64 t, %1; cvt.u32.u64 %0, t; }" : "=r"(a) : "l"(p));
    return a;
}
__device__ __forceinline__ void ldm_x4(uint32_t& r0, uint32_t& r1, uint32_t& r2, uint32_t& r3, uint32_t a) {
    asm volatile("ldmatrix.sync.aligned.m8n8.x4.shared.b16 {%0,%1,%2,%3}, [%4];"
                 : "=r"(r0), "=r"(r1), "=r"(r2), "=r"(r3) : "r"(a));
}
__device__ __forceinline__ void ldm_x2(uint32_t& r0, uint32_t& r1, uint32_t a) {
    asm volatile("ldmatrix.sync.aligned.m8n8.x2.shared.b16 {%0,%1}, [%2];"
                 : "=r"(r0), "=r"(r1) : "r"(a));
}
__device__ __forceinline__ void mma16816(float* c, const uint32_t* a, const uint32_t* b) {
    asm volatile("mma.sync.aligned.m16n8k16.row.col.f32.bf16.bf16.f32 "
                 "{%0,%1,%2,%3}, {%4,%5,%6,%7}, {%8,%9}, {%0,%1,%2,%3};"
                 : "+f"(c[0]), "+f"(c[1]), "+f"(c[2]), "+f"(c[3])
                 : "r"(a[0]), "r"(a[1]), "r"(a[2]), "r"(a[3]), "r"(b[0]), "r"(b[1]));
}

// ---------------- LayerNorm -> split bf16 hi/lo ----------------
__global__ void ln_kernel(const float* __restrict__ x,
                          const float* __restrict__ g,
                          const float* __restrict__ b,
                          __nv_bfloat16* __restrict__ oh,
                          __nv_bfloat16* __restrict__ ol)
{
    const int row = blockIdx.x;
    const float* xr = x + (size_t)row * DD;

    float s = 0.f, s2 = 0.f;
    for (int i = threadIdx.x; i < DD; i += blockDim.x) {
        float v = xr[i];
        s += v; s2 += v * v;
    }
    __shared__ float red[64];
    for (int o = 16; o; o >>= 1) {
        s  += __shfl_xor_sync(0xffffffffu, s,  o);
        s2 += __shfl_xor_sync(0xffffffffu, s2, o);
    }
    int wid = threadIdx.x >> 5, lid = threadIdx.x & 31;
    if (lid == 0) { red[wid] = s; red[wid + 32] = s2; }
    __syncthreads();
    if (wid == 0) {
        int nw = blockDim.x >> 5;
        s  = (lid < nw) ? red[lid] : 0.f;
        s2 = (lid < nw) ? red[lid + 32] : 0.f;
        for (int o = 16; o; o >>= 1) {
            s  += __shfl_xor_sync(0xffffffffu, s,  o);
            s2 += __shfl_xor_sync(0xffffffffu, s2, o);
        }
        if (lid == 0) { red[0] = s; red[1] = s2; }
    }
    __syncthreads();
    float mean = red[0] * (1.0f / DD);
    float var  = red[1] * (1.0f / DD) - mean * mean;
    float inv  = rsqrtf(var + 1e-5f);
    for (int i = threadIdx.x; i < DD; i += blockDim.x) {
        float v = (xr[i] - mean) * inv * g[i] + b[i];
        __nv_bfloat16 h = __float2bfloat16(v);
        oh[(size_t)row * DD + i] = h;
        ol[(size_t)row * DD + i] = __float2bfloat16(v - __bfloat162float(h));
    }
}

// ---------------- weight transpose + split: w[K,N] -> th/tl[N,K] ----------
__global__ void wprep_kernel(const float* __restrict__ w,
                             __nv_bfloat16* __restrict__ th,
                             __nv_bfloat16* __restrict__ tl, int K, int N)
{
    __shared__ float t[32][33];
    int nx0 = blockIdx.x * 32, ky0 = blockIdx.y * 32;
    int tx = threadIdx.x, ty = threadIdx.y;   // 32 x 8
    #pragma unroll
    for (int d = 0; d < 4; d++)
        t[ty + d * 8][tx] = w[(size_t)(ky0 + ty + d * 8) * N + nx0 + tx];
    __syncthreads();
    #pragma unroll
    for (int d = 0; d < 4; d++) {
        float v = t[tx][ty + d * 8];
        __nv_bfloat16 h = __float2bfloat16(v);
        size_t o = (size_t)(nx0 + ty + d * 8) * K + ky0 + tx;
        th[o] = h;
        tl[o] = __float2bfloat16(v - __bfloat162float(h));
    }
}

// ---------------- mma.sync split-bf16 GEMM ----------------
// C[M,N] = (Ah+Al)[M,K] @ (Bh+Bl)[N,K]^T, fp32 accum.
// CTA tile 128x128, BK=32, 256 threads (8 warps 2m x 4n, warp tile 64x32).
#define LDT 40   // smem row stride in elems (32 + 8 pad) -> 80B, conflict-free

__global__ void __launch_bounds__(256, 1)
mma_gemm(const __nv_bfloat16* __restrict__ Ah, const __nv_bfloat16* __restrict__ Al,
         const __nv_bfloat16* __restrict__ Bh, const __nv_bfloat16* __restrict__ Bl,
         const float* __restrict__ bias, const float* __restrict__ resid,
         float* __restrict__ Cf, __nv_bfloat16* __restrict__ Ch,
         __nv_bfloat16* __restrict__ Cl, int M, int N, int K, int dogelu)
{
    __shared__ __nv_bfloat16 sAh[128 * LDT], sAl[128 * LDT];
    __shared__ __nv_bfloat16 sBh[128 * LDT], sBl[128 * LDT];

    const int tid = threadIdx.x, lane = tid & 31, wid = tid >> 5;
    const int wm = wid & 1, wn = wid >> 1;           // warp 64m x 32n
    const int bm = blockIdx.y * 128, bn = blockIdx.x * 128;

    float acc[4][4][4];
    #pragma unroll
    for (int i = 0; i < 4; i++)
        #pragma unroll
        for (int j = 0; j < 4; j++)
            #pragma unroll
            for (int r = 0; r < 4; r++) acc[i][j][r] = 0.f;

    const uint32_t sAh_b = smem_u32(sAh), sAl_b = smem_u32(sAl);
    const uint32_t sBh_b = smem_u32(sBh), sBl_b = smem_u32(sBl);

    // ldmatrix lane addresses (byte offsets within tile)
    // A x4: row = lane&15 (+ tile m), col = (lane>>4)*8 (+ ks*16)
    const uint32_t a_off = (uint32_t)((lane & 15) * LDT + (lane >> 4) * 8) * 2;
    // B x2: row = lane&7 (+ tile n), col = ((lane>>3)&1)*8 (+ ks*16)
    const uint32_t b_off = (uint32_t)((lane & 7) * LDT + ((lane >> 3) & 1) * 8) * 2;

    for (int k0 = 0; k0 < K; k0 += 32) {
        // load 4 tiles of 128x32 bf16; 2 uint4 per thread per tile
        #pragma unroll
        for (int u = 0; u < 2; u++) {
            int idx = tid + u * 256;        // 0..511
            int r = idx >> 2, c8 = (idx & 3) * 8;
            size_t ga = (size_t)(bm + r) * K + k0 + c8;
            size_t gb = (size_t)(bn + r) * K + k0 + c8;
            int so = r * LDT + c8;
            *(uint4*)(sAh + so) = *(const uint4*)(Ah + ga);
            *(uint4*)(sAl + so) = *(const uint4*)(Al + ga);
            *(uint4*)(sBh + so) = *(const uint4*)(Bh + gb);
            *(uint4*)(sBl + so) = *(const uint4*)(Bl + gb);
        }
        __syncthreads();

        #pragma unroll
        for (int ks = 0; ks < 2; ks++) {
            const uint32_t kso = ks * 16 * 2;
            uint32_t ah[4][4], al[4][4], bh[4][2], bl[4][2];
            #pragma unroll
            for (int mt = 0; mt < 4; mt++) {
                uint32_t base = (uint32_t)((wm * 64 + mt * 16) * LDT) * 2 + kso + a_off;
                ldm_x4(ah[mt][0], ah[mt][1], ah[mt][2], ah[mt][3], sAh_b + base);
                ldm_x4(al[mt][0], al[mt][1], al[mt][2], al[mt][3], sAl_b + base);
            }
            #pragma unroll
            for (int nt = 0; nt < 4; nt++) {
                uint32_t base = (uint32_t)((wn * 32 + nt * 8) * LDT) * 2 + kso + b_off;
                ldm_x2(bh[nt][0], bh[nt][1], sBh_b + base);
                ldm_x2(bl[nt][0], bl[nt][1], sBl_b + base);
            }
            #pragma unroll
            for (int mt = 0; mt < 4; mt++)
                #pragma unroll
                for (int nt = 0; nt < 4; nt++) {
                    mma16816(acc[mt][nt], ah[mt], bh[nt]);
                    mma16816(acc[mt][nt], ah[mt], bl[nt]);
                    mma16816(acc[mt][nt], al[mt], bh[nt]);
                }
        }
        __syncthreads();
    }

    // epilogue: frag (mt,nt): c0,c1 -> (m = mt*16 + lane/4,    n = nt*8 + (lane&3)*2 + {0,1})
    //                         c2,c3 -> (m = mt*16 + lane/4 + 8, same n)
    const int mrow = bm + wm * 64 + (lane >> 2);
    const int ncol = bn + wn * 32 + (lane & 3) * 2;
    #pragma unroll
    for (int mt = 0; mt < 4; mt++) {
        #pragma unroll
        for (int half = 0; half < 2; half++) {
            int row = mrow + mt * 16 + half * 8;
            #pragma unroll
            for (int nt = 0; nt < 4; nt++) {
                int col = ncol + nt * 8;
                float v0 = acc[mt][nt][half * 2 + 0];
                float v1 = acc[mt][nt][half * 2 + 1];
                if (bias) { v0 += __ldg(bias + col); v1 += __ldg(bias + col + 1); }
                if (dogelu) {
                    v0 = 0.5f * v0 * (1.0f + erff(v0 * 0.70710678118654752f));
                    v1 = 0.5f * v1 * (1.0f + erff(v1 * 0.70710678118654752f));
                }
                size_t o = (size_t)row * N + col;
                if (resid) { v0 += resid[o]; v1 += resid[o + 1]; }
                if (Cf) { *(float2*)(Cf + o) = make_float2(v0, v1); }
                if (Ch) {
                    __nv_bfloat16 h0 = __float2bfloat16(v0);
                    __nv_bfloat16 h1 = __float2bfloat16(v1);
                    __nv_bfloat162 hp; hp.x = h0; hp.y = h1;
                    __nv_bfloat162 lp;
                    lp.x = __float2bfloat16(v0 - __bfloat162float(h0));
                    lp.y = __float2bfloat16(v1 - __bfloat162float(h1));
                    *(__nv_bfloat162*)(Ch + o) = hp;
                    *(__nv_bfloat162*)(Cl + o) = lp;
                }
            }
        }
    }
}

// ---------------- Flash attention (fp32, online softmax) ----------------
// mask is int32 (bool promoted): nonzero = attend. Writes bf16 hi/lo output.
__global__ void __launch_bounds__(128, 2)
flash_kernel(const float* __restrict__ Q, const float* __restrict__ K,
             const float* __restrict__ V, const int* __restrict__ mask,
             __nv_bfloat16* __restrict__ Oh, __nv_bfloat16* __restrict__ Ol)
{
    const int BKV = 32;
    __shared__ float Ks[BKV][HD];
    __shared__ float Vs[BKV][HD];

    const int b = blockIdx.z, hh = blockIdx.y;
    const int tid = threadIdx.x;
    const int qi = blockIdx.x * 128 + tid;

    const float* qp = Q + ((size_t)(b * SS + qi)) * DD + hh * HD;
    float q[HD];
    #pragma unroll
    for (int i = 0; i < 16; i++)
        *(float4*)(q + 4 * i) = *(const float4*)(qp + 4 * i);

    float acc[HD];
    #pragma unroll
    for (int d = 0; d < HD; d++) acc[d] = 0.f;
    float m = -INFINITY, l = 0.f;
    int any = 0;

    const int* mrow = mask + ((size_t)(b * SS + qi)) * SS;

    for (int t0 = 0; t0 < SS; t0 += BKV) {
        #pragma unroll
        for (int u = 0; u < 4; u++) {
            int f = tid + u * 128;
            int r = f >> 4, c = (f & 15) * 4;
            size_t base = ((size_t)(b * SS + t0 + r)) * DD + hh * HD + c;
            *(float4*)(&Ks[r][c]) = *(const float4*)(K + base);
            *(float4*)(&Vs[r][c]) = *(const float4*)(V + base);
        }
        __syncthreads();

        float s[BKV];
        float tmax = -INFINITY;
        #pragma unroll
        for (int kk = 0; kk < BKV; kk++) {
            float dot = 0.f;
            #pragma unroll
            for (int d4 = 0; d4 < 16; d4++) {
                float4 kv = *(const float4*)(&Ks[kk][d4 * 4]);
                dot += q[d4*4+0] * kv.x + q[d4*4+1] * kv.y
                     + q[d4*4+2] * kv.z + q[d4*4+3] * kv.w;
            }
            dot *= 0.125f;
            int mb = mrow[t0 + kk];
            any |= mb;
            s[kk] = mb ? dot : -1e30f;
            tmax = fmaxf(tmax, s[kk]);
        }

        float mnew = fmaxf(m, tmax);
        float corr = __expf(m - mnew);
        l *= corr;
        #pragma unroll
        for (int d = 0; d < HD; d++) acc[d] *= corr;

        #pragma unroll
        for (int kk = 0; kk < BKV; kk++) {
            float p = __expf(s[kk] - mnew);
            l += p;
            #pragma unroll
            for (int d4 = 0; d4 < 16; d4++) {
                float4 vv = *(const float4*)(&Vs[kk][d4 * 4]);
                acc[d4*4+0] += p * vv.x; acc[d4*4+1] += p * vv.y;
                acc[d4*4+2] += p * vv.z; acc[d4*4+3] += p * vv.w;
            }
        }
        m = mnew;
        __syncthreads();
    }

    float invl = (any && l > 0.f) ? (1.0f / l) : 0.0f;
    size_t ob = ((size_t)(b * SS + qi)) * DD + hh * HD;
    #pragma unroll
    for (int d = 0; d < HD; d++) {
        float v = acc[d] * invl;
        __nv_bfloat16 h = __float2bfloat16(v);
        Oh[ob + d] = h;
        Ol[ob + d] = __float2bfloat16(v - __bfloat162float(h));
    }
}

// ---------------- launch ----------------
extern "C" void kernel_launch(void* const* d_in, const int* in_sizes, int n_in,
                              void* d_out, int out_size)
{
    const float* x      = (const float*)d_in[0];
    const int*   mask   = (const int*)d_in[1];
    const float* ln1_g  = (const float*)d_in[2];
    const float* ln1_b  = (const float*)d_in[3];
    const float* wq     = (const float*)d_in[4];
    const float* wk     = (const float*)d_in[5];
    const float* wv     = (const float*)d_in[6];
    const float* wo     = (const float*)d_in[7];
    const float* bo     = (const float*)d_in[8];
    const float* ln2_g  = (const float*)d_in[9];
    const float* ln2_b  = (const float*)d_in[10];
    const float* w1     = (const float*)d_in[11];
    const float* b1     = (const float*)d_in[12];
    const float* w2     = (const float*)d_in[13];
    const float* b2     = (const float*)d_in[14];
    float* out = (float*)d_out;

    __nv_bfloat16 *lnh, *lnl, *atth, *attl, *hh, *hl;
    __nv_bfloat16 *wqh, *wql, *wkh, *wkl, *wvh, *wvl, *woh, *wol, *w1h, *w1l, *w2h, *w2l;
    float *q, *k, *v, *x1;
    cudaGetSymbolAddress((void**)&lnh,  g_lnh);  cudaGetSymbolAddress((void**)&lnl,  g_lnl);
    cudaGetSymbolAddress((void**)&q,    g_q);    cudaGetSymbolAddress((void**)&k,    g_k);
    cudaGetSymbolAddress((void**)&v,    g_v);
    cudaGetSymbolAddress((void**)&atth, g_atth); cudaGetSymbolAddress((void**)&attl, g_attl);
    cudaGetSymbolAddress((void**)&x1,   g_x1);
    cudaGetSymbolAddress((void**)&hh,   g_hh);   cudaGetSymbolAddress((void**)&hl,   g_hl);
    cudaGetSymbolAddress((void**)&wqh,  g_wqh);  cudaGetSymbolAddress((void**)&wql,  g_wql);
    cudaGetSymbolAddress((void**)&wkh,  g_wkh);  cudaGetSymbolAddress((void**)&wkl,  g_wkl);
    cudaGetSymbolAddress((void**)&wvh,  g_wvh);  cudaGetSymbolAddress((void**)&wvl,  g_wvl);
    cudaGetSymbolAddress((void**)&woh,  g_woh);  cudaGetSymbolAddress((void**)&wol,  g_wol);
    cudaGetSymbolAddress((void**)&w1h,  g_w1h);  cudaGetSymbolAddress((void**)&w1l,  g_w1l);
    cudaGetSymbolAddress((void**)&w2h,  g_w2h);  cudaGetSymbolAddress((void**)&w2l,  g_w2l);

    // 0) weight transpose + split (hi/lo bf16, [N,K])
    dim3 tb(32, 8);
    wprep_kernel<<<dim3(DD/32, DD/32), tb>>>(wq, wqh, wql, DD, DD);
    wprep_kernel<<<dim3(DD/32, DD/32), tb>>>(wk, wkh, wkl, DD, DD);
    wprep_kernel<<<dim3(DD/32, DD/32), tb>>>(wv, wvh, wvl, DD, DD);
    wprep_kernel<<<dim3(DD/32, DD/32), tb>>>(wo, woh, wol, DD, DD);
    wprep_kernel<<<dim3(FF/32, DD/32), tb>>>(w1, w1h, w1l, DD, FF);
    wprep_kernel<<<dim3(DD/32, FF/32), tb>>>(w2, w2h, w2l, FF, DD);

    // 1) LN1 -> split
    ln_kernel<<<ROWS, 256>>>(x, ln1_g, ln1_b, lnh, lnl);

    // 2) Q,K,V projections (tensor cores via mma.sync)
    dim3 gQKV(DD/128, ROWS/128);
    mma_gemm<<<gQKV, 256>>>(lnh, lnl, wqh, wql, nullptr, nullptr, q, nullptr, nullptr, ROWS, DD, DD, 0);
    mma_gemm<<<gQKV, 256>>>(lnh, lnl, wkh, wkl, nullptr, nullptr, k, nullptr, nullptr, ROWS, DD, DD, 0);
    mma_gemm<<<gQKV, 256>>>(lnh, lnl, wvh, wvl, nullptr, nullptr, v, nullptr, nullptr, ROWS, DD, DD, 0);

    // 3) attention -> split output
    dim3 gF(SS/128, HH, BB);
    flash_kernel<<<gF, 128>>>(q, k, v, mask, atth, attl);

    // 4) output projection + bias + residual -> x1 (fp32)
    mma_gemm<<<gQKV, 256>>>(atth, attl, woh, wol, bo, x, x1, nullptr, nullptr, ROWS, DD, DD, 0);

    // 5) LN2 -> split
    ln_kernel<<<ROWS, 256>>>(x1, ln2_g, ln2_b, lnh, lnl);

    // 6) MLP up + bias + gelu -> split h
    dim3 gM1(FF/128, ROWS/128);
    mma_gemm<<<gM1, 256>>>(lnh, lnl, w1h, w1l, b1, nullptr, nullptr, hh, hl, ROWS, FF, DD, 1);

    // 7) MLP down + bias + residual -> out
    dim3 gM2(DD/128, ROWS/128);
    mma_gemm<<<gM2, 256>>>(hh, hl, w2h, w2l, b2, x1, out, nullptr, nullptr, ROWS, DD, FF, 0);
}

// round 8
// speedup vs baseline: 2.7038x; 2.0734x over previous
#include <cuda_runtime.h>
#include <cuda_bf16.h>
#include <math.h>
#include <stdint.h>

// Problem constants
#define BB 4
#define SS 2048
#define DD 1024
#define HH 16
#define HD 64
#define FF 4096
#define ROWS (BB*SS)          // 8192

// ---------------- scratch (device globals; no allocation) ----------------
__device__ __nv_bfloat16 g_lnh[(size_t)ROWS * DD];
__device__ __nv_bfloat16 g_lnl[(size_t)ROWS * DD];
__device__ __nv_bfloat16 g_qh [(size_t)ROWS * DD], g_ql [(size_t)ROWS * DD];
__device__ __nv_bfloat16 g_kh [(size_t)ROWS * DD], g_kl [(size_t)ROWS * DD];
__device__ __nv_bfloat16 g_vh [(size_t)ROWS * DD], g_vl [(size_t)ROWS * DD];
__device__ __nv_bfloat16 g_atth[(size_t)ROWS * DD];
__device__ __nv_bfloat16 g_attl[(size_t)ROWS * DD];
__device__ float g_x1[(size_t)ROWS * DD];
__device__ __nv_bfloat16 g_hh[(size_t)ROWS * FF];
__device__ __nv_bfloat16 g_hl[(size_t)ROWS * FF];
// transposed + split weights: wt[N][K]
__device__ __nv_bfloat16 g_wqh[(size_t)DD*DD], g_wql[(size_t)DD*DD];
__device__ __nv_bfloat16 g_wkh[(size_t)DD*DD], g_wkl[(size_t)DD*DD];
__device__ __nv_bfloat16 g_wvh[(size_t)DD*DD], g_wvl[(size_t)DD*DD];
__device__ __nv_bfloat16 g_woh[(size_t)DD*DD], g_wol[(size_t)DD*DD];
__device__ __nv_bfloat16 g_w1h[(size_t)DD*FF], g_w1l[(size_t)DD*FF];
__device__ __nv_bfloat16 g_w2h[(size_t)FF*DD], g_w2l[(size_t)FF*DD];

// ---------------- helpers ----------------
__device__ __forceinline__ uint32_t smem_u32(const void* p) {
    uint32_t a;
    asm("{ .reg .u64 t; cvta.to.shared.u64 t, %1; cvt.u32.u64 %0, t; }" : "=r"(a) : "l"(p));
    return a;
}
__device__ __forceinline__ void ldm_x4(uint32_t& r0, uint32_t& r1, uint32_t& r2, uint32_t& r3, uint32_t a) {
    asm volatile("ldmatrix.sync.aligned.m8n8.x4.shared.b16 {%0,%1,%2,%3}, [%4];"
                 : "=r"(r0), "=r"(r1), "=r"(r2), "=r"(r3) : "r"(a));
}
__device__ __forceinline__ void ldm_x4_t(uint32_t& r0, uint32_t& r1, uint32_t& r2, uint32_t& r3, uint32_t a) {
    asm volatile("ldmatrix.sync.aligned.m8n8.x4.trans.shared.b16 {%0,%1,%2,%3}, [%4];"
                 : "=r"(r0), "=r"(r1), "=r"(r2), "=r"(r3) : "r"(a));
}
__device__ __forceinline__ void ldm_x2(uint32_t& r0, uint32_t& r1, uint32_t a) {
    asm volatile("ldmatrix.sync.aligned.m8n8.x2.shared.b16 {%0,%1}, [%2];"
                 : "=r"(r0), "=r"(r1) : "r"(a));
}
__device__ __forceinline__ void mma16816(float* c, const uint32_t* a, const uint32_t* b) {
    asm volatile("mma.sync.aligned.m16n8k16.row.col.f32.bf16.bf16.f32 "
                 "{%0,%1,%2,%3}, {%4,%5,%6,%7}, {%8,%9}, {%0,%1,%2,%3};"
                 : "+f"(c[0]), "+f"(c[1]), "+f"(c[2]), "+f"(c[3])
                 : "r"(a[0]), "r"(a[1]), "r"(a[2]), "r"(a[3]), "r"(b[0]), "r"(b[1]));
}
__device__ __forceinline__ uint32_t pack2(float a, float b) {
    __nv_bfloat162 t = __floats2bfloat162_rn(a, b);
    return *(uint32_t*)&t;
}
#define CP_ASYNC16(dst, src) asm volatile("cp.async.cg.shared.global [%0], [%1], 16;" :: "r"(dst), "l"(src))
#define CP_COMMIT()  asm volatile("cp.async.commit_group;")
#define CP_WAIT0()   asm volatile("cp.async.wait_group 0;")
#define CP_WAIT1()   asm volatile("cp.async.wait_group 1;")

// ---------------- LayerNorm -> split bf16 hi/lo ----------------
__global__ void ln_kernel(const float* __restrict__ x,
                          const float* __restrict__ g,
                          const float* __restrict__ b,
                          __nv_bfloat16* __restrict__ oh,
                          __nv_bfloat16* __restrict__ ol)
{
    const int row = blockIdx.x;
    const float* xr = x + (size_t)row * DD;

    float s = 0.f, s2 = 0.f;
    for (int i = threadIdx.x; i < DD; i += blockDim.x) {
        float v = xr[i];
        s += v; s2 += v * v;
    }
    __shared__ float red[64];
    for (int o = 16; o; o >>= 1) {
        s  += __shfl_xor_sync(0xffffffffu, s,  o);
        s2 += __shfl_xor_sync(0xffffffffu, s2, o);
    }
    int wid = threadIdx.x >> 5, lid = threadIdx.x & 31;
    if (lid == 0) { red[wid] = s; red[wid + 32] = s2; }
    __syncthreads();
    if (wid == 0) {
        int nw = blockDim.x >> 5;
        s  = (lid < nw) ? red[lid] : 0.f;
        s2 = (lid < nw) ? red[lid + 32] : 0.f;
        for (int o = 16; o; o >>= 1) {
            s  += __shfl_xor_sync(0xffffffffu, s,  o);
            s2 += __shfl_xor_sync(0xffffffffu, s2, o);
        }
        if (lid == 0) { red[0] = s; red[1] = s2; }
    }
    __syncthreads();
    float mean = red[0] * (1.0f / DD);
    float var  = red[1] * (1.0f / DD) - mean * mean;
    float inv  = rsqrtf(var + 1e-5f);
    for (int i = threadIdx.x; i < DD; i += blockDim.x) {
        float v = (xr[i] - mean) * inv * g[i] + b[i];
        __nv_bfloat16 h = __float2bfloat16(v);
        oh[(size_t)row * DD + i] = h;
        ol[(size_t)row * DD + i] = __float2bfloat16(v - __bfloat162float(h));
    }
}

// ---------------- weight transpose + split: w[K,N] -> th/tl[N,K] ----------
__global__ void wprep_kernel(const float* __restrict__ w,
                             __nv_bfloat16* __restrict__ th,
                             __nv_bfloat16* __restrict__ tl, int K, int N)
{
    __shared__ float t[32][33];
    int nx0 = blockIdx.x * 32, ky0 = blockIdx.y * 32;
    int tx = threadIdx.x, ty = threadIdx.y;   // 32 x 8
    #pragma unroll
    for (int d = 0; d < 4; d++)
        t[ty + d * 8][tx] = w[(size_t)(ky0 + ty + d * 8) * N + nx0 + tx];
    __syncthreads();
    #pragma unroll
    for (int d = 0; d < 4; d++) {
        float v = t[tx][ty + d * 8];
        __nv_bfloat16 h = __float2bfloat16(v);
        size_t o = (size_t)(nx0 + ty + d * 8) * K + ky0 + tx;
        th[o] = h;
        tl[o] = __float2bfloat16(v - __bfloat162float(h));
    }
}

// ---------------- mma.sync split-bf16 GEMM, cp.async double-buffered -----
// C[M,N] = (Ah+Al)[M,K] @ (Bh+Bl)[N,K]^T, fp32 accum.
// CTA tile 128x128, BK=32, 256 threads (8 warps 2m x 4n, warp tile 64x32).
#define LDT 40         // smem row stride in elems (32 + 8 pad) -> 80B
#define GARR (128*LDT*2)          // 10240 B per array
#define GSTG (4*GARR)             // 40960 B per stage
#define SMEM_GEMM (2*GSTG)        // 81920 B

__global__ void __launch_bounds__(256, 1)
mma_gemm(const __nv_bfloat16* __restrict__ Ah, const __nv_bfloat16* __restrict__ Al,
         const __nv_bfloat16* __restrict__ Bh, const __nv_bfloat16* __restrict__ Bl,
         const float* __restrict__ bias, const float* __restrict__ resid,
         float* __restrict__ Cf, __nv_bfloat16* __restrict__ Ch,
         __nv_bfloat16* __restrict__ Cl, int M, int N, int K, int dogelu)
{
    extern __shared__ char gsm[];
    const uint32_t sb = smem_u32(gsm);

    const int tid = threadIdx.x, lane = tid & 31, wid = tid >> 5;
    const int wm = wid & 1, wn = wid >> 1;           // warp 64m x 32n
    const int bm = blockIdx.y * 128, bn = blockIdx.x * 128;

    float acc[4][4][4];
    #pragma unroll
    for (int i = 0; i < 4; i++)
        #pragma unroll
        for (int j = 0; j < 4; j++)
            #pragma unroll
            for (int r = 0; r < 4; r++) acc[i][j][r] = 0.f;

    // per-thread load coords (2 uint4 per array per stage)
    const int l_r0 = tid >> 2, l_c8 = (tid & 3) * 8;   // +64 rows for u=1
    // ldmatrix lane offsets
    const uint32_t a_off = (uint32_t)((lane & 15) * LDT + (lane >> 4) * 8) * 2;
    const uint32_t b_off = (uint32_t)((lane & 7) * LDT + ((lane >> 3) & 1) * 8) * 2;

    const int T = K >> 5;

    // prologue: stage 0
    {
        #pragma unroll
        for (int u = 0; u < 2; u++) {
            int r = l_r0 + u * 64;
            uint32_t so = (uint32_t)(r * LDT + l_c8) * 2;
            size_t ga = (size_t)(bm + r) * K + l_c8;
            size_t gb = (size_t)(bn + r) * K + l_c8;
            CP_ASYNC16(sb + 0*GARR + so, Ah + ga);
            CP_ASYNC16(sb + 1*GARR + so, Al + ga);
            CP_ASYNC16(sb + 2*GARR + so, Bh + gb);
            CP_ASYNC16(sb + 3*GARR + so, Bl + gb);
        }
        CP_COMMIT();
    }

    for (int t = 0; t < T; t++) {
        if (t + 1 < T) {
            const int kn = (t + 1) << 5;
            const uint32_t st = ((t + 1) & 1) ? GSTG : 0;
            #pragma unroll
            for (int u = 0; u < 2; u++) {
                int r = l_r0 + u * 64;
                uint32_t so = st + (uint32_t)(r * LDT + l_c8) * 2;
                size_t ga = (size_t)(bm + r) * K + kn + l_c8;
                size_t gb = (size_t)(bn + r) * K + kn + l_c8;
                CP_ASYNC16(sb + 0*GARR + so, Ah + ga);
                CP_ASYNC16(sb + 1*GARR + so, Al + ga);
                CP_ASYNC16(sb + 2*GARR + so, Bh + gb);
                CP_ASYNC16(sb + 3*GARR + so, Bl + gb);
            }
            CP_COMMIT();
            CP_WAIT1();
        } else {
            CP_WAIT0();
        }
        __syncthreads();

        const uint32_t st = (t & 1) ? GSTG : 0;
        const uint32_t sAh_b = sb + st, sAl_b = sb + st + GARR;
        const uint32_t sBh_b = sb + st + 2*GARR, sBl_b = sb + st + 3*GARR;

        #pragma unroll
        for (int ks = 0; ks < 2; ks++) {
            const uint32_t kso = ks * 16 * 2;
            uint32_t ah[4][4], al[4][4], bh[4][2], bl[4][2];
            #pragma unroll
            for (int mt = 0; mt < 4; mt++) {
                uint32_t base = (uint32_t)((wm * 64 + mt * 16) * LDT) * 2 + kso + a_off;
                ldm_x4(ah[mt][0], ah[mt][1], ah[mt][2], ah[mt][3], sAh_b + base);
                ldm_x4(al[mt][0], al[mt][1], al[mt][2], al[mt][3], sAl_b + base);
            }
            #pragma unroll
            for (int nt = 0; nt < 4; nt++) {
                uint32_t base = (uint32_t)((wn * 32 + nt * 8) * LDT) * 2 + kso + b_off;
                ldm_x2(bh[nt][0], bh[nt][1], sBh_b + base);
                ldm_x2(bl[nt][0], bl[nt][1], sBl_b + base);
            }
            #pragma unroll
            for (int mt = 0; mt < 4; mt++)
                #pragma unroll
                for (int nt = 0; nt < 4; nt++) {
                    mma16816(acc[mt][nt], ah[mt], bh[nt]);
                    mma16816(acc[mt][nt], ah[mt], bl[nt]);
                    mma16816(acc[mt][nt], al[mt], bh[nt]);
                }
        }
        __syncthreads();
    }

    // epilogue
    const int mrow = bm + wm * 64 + (lane >> 2);
    const int ncol = bn + wn * 32 + (lane & 3) * 2;
    #pragma unroll
    for (int mt = 0; mt < 4; mt++) {
        #pragma unroll
        for (int half = 0; half < 2; half++) {
            int row = mrow + mt * 16 + half * 8;
            #pragma unroll
            for (int nt = 0; nt < 4; nt++) {
                int col = ncol + nt * 8;
                float v0 = acc[mt][nt][half * 2 + 0];
                float v1 = acc[mt][nt][half * 2 + 1];
                if (bias) { v0 += __ldg(bias + col); v1 += __ldg(bias + col + 1); }
                if (dogelu) {
                    v0 = 0.5f * v0 * (1.0f + erff(v0 * 0.70710678118654752f));
                    v1 = 0.5f * v1 * (1.0f + erff(v1 * 0.70710678118654752f));
                }
                size_t o = (size_t)row * N + col;
                if (resid) { v0 += resid[o]; v1 += resid[o + 1]; }
                if (Cf) { *(float2*)(Cf + o) = make_float2(v0, v1); }
                if (Ch) {
                    __nv_bfloat16 h0 = __float2bfloat16(v0);
                    __nv_bfloat16 h1 = __float2bfloat16(v1);
                    __nv_bfloat162 hp; hp.x = h0; hp.y = h1;
                    __nv_bfloat162 lp;
                    lp.x = __float2bfloat16(v0 - __bfloat162float(h0));
                    lp.y = __float2bfloat16(v1 - __bfloat162float(h1));
                    *(__nv_bfloat162*)(Ch + o) = hp;
                    *(__nv_bfloat162*)(Cl + o) = lp;
                }
            }
        }
    }
}

// ---------------- Flash attention, mma.sync split-bf16 -------------------
// CTA: 64 q-rows x one head. 4 warps, warp owns 16 q-rows.
// S = Qh.Kh + Qh.Kl + Ql.Kh ; O += Ph.Vh + Ph.Vl + Pl.Vh (fp32 accum).
#define LDF 72
#define FOFF_QH 0
#define FOFF_QL 9216
#define FOFF_KH 18432
#define FOFF_KL 27648
#define FOFF_VH 36864
#define FOFF_VL 46080
#define FOFF_MK 55296
#define SMEM_FLASH (55296 + 16384)

__global__ void __launch_bounds__(128, 2)
flash_mma(const __nv_bfloat16* __restrict__ Qh, const __nv_bfloat16* __restrict__ Ql,
          const __nv_bfloat16* __restrict__ Kh, const __nv_bfloat16* __restrict__ Kl,
          const __nv_bfloat16* __restrict__ Vh, const __nv_bfloat16* __restrict__ Vl,
          const int* __restrict__ mask,
          __nv_bfloat16* __restrict__ Oh, __nv_bfloat16* __restrict__ Ol)
{
    extern __shared__ char fsm[];
    __nv_bfloat16* sqh = (__nv_bfloat16*)(fsm + FOFF_QH);
    __nv_bfloat16* sql = (__nv_bfloat16*)(fsm + FOFF_QL);
    __nv_bfloat16* skh = (__nv_bfloat16*)(fsm + FOFF_KH);
    __nv_bfloat16* skl = (__nv_bfloat16*)(fsm + FOFF_KL);
    __nv_bfloat16* svh = (__nv_bfloat16*)(fsm + FOFF_VH);
    __nv_bfloat16* svl = (__nv_bfloat16*)(fsm + FOFF_VL);
    int* smsk = (int*)(fsm + FOFF_MK);

    const int b = blockIdx.z, h = blockIdx.y;
    const int q0 = blockIdx.x * 64;
    const int tid = threadIdx.x, lane = tid & 31, w = tid >> 5;

    // load Q tile 64x64 hi/lo
    #pragma unroll
    for (int j = 0; j < 4; j++) {
        int e = tid + j * 128;
        int r = e >> 3, c8 = (e & 7) * 8;
        size_t g = (size_t)(b * SS + q0 + r) * DD + h * HD + c8;
        *(uint4*)(sqh + r * LDF + c8) = *(const uint4*)(Qh + g);
        *(uint4*)(sql + r * LDF + c8) = *(const uint4*)(Ql + g);
    }
    __syncthreads();

    const uint32_t sqh_b = smem_u32(sqh), sql_b = smem_u32(sql);
    const uint32_t skh_b = smem_u32(skh), skl_b = smem_u32(skl);
    const uint32_t svh_b = smem_u32(svh), svl_b = smem_u32(svl);
    const uint32_t a_off = (uint32_t)((lane & 15) * LDF + (lane >> 4) * 8) * 2;
    const uint32_t b_off = (uint32_t)((lane & 7) * LDF + ((lane >> 3) & 1) * 8) * 2;

    uint32_t qhf[4][4], qlf[4][4];
    #pragma unroll
    for (int ks = 0; ks < 4; ks++) {
        uint32_t base = (uint32_t)(w * 16 * LDF) * 2 + (uint32_t)(ks * 16) * 2 + a_off;
        ldm_x4(qhf[ks][0], qhf[ks][1], qhf[ks][2], qhf[ks][3], sqh_b + base);
        ldm_x4(qlf[ks][0], qlf[ks][1], qlf[ks][2], qlf[ks][3], sql_b + base);
    }

    float oacc[8][4];
    #pragma unroll
    for (int i = 0; i < 8; i++)
        #pragma unroll
        for (int j = 0; j < 4; j++) oacc[i][j] = 0.f;
    float m0 = -INFINITY, m1 = -INFINITY, l0 = 0.f, l1 = 0.f;
    int any0 = 0, any1 = 0;
    const int lr0 = lane >> 2;            // local row in warp tile (r1 = lr0+8)

    for (int t0 = 0; t0 < SS; t0 += 64) {
        __syncthreads();
        // load K/V tiles hi/lo (both [key][dim], dim contiguous)
        #pragma unroll
        for (int j = 0; j < 4; j++) {
            int e = tid + j * 128;
            int r = e >> 3, c8 = (e & 7) * 8;
            size_t g = (size_t)(b * SS + t0 + r) * DD + h * HD + c8;
            *(uint4*)(skh + r * LDF + c8) = *(const uint4*)(Kh + g);
            *(uint4*)(skl + r * LDF + c8) = *(const uint4*)(Kl + g);
            *(uint4*)(svh + r * LDF + c8) = *(const uint4*)(Vh + g);
            *(uint4*)(svl + r * LDF + c8) = *(const uint4*)(Vl + g);
        }
        // mask tile 64 rows x 64 keys (int)
        #pragma unroll
        for (int j = 0; j < 8; j++) {
            int e = tid + j * 128;            // 1024 int4
            int r = e >> 4, c4 = (e & 15) * 4;
            *(int4*)(smsk + r * 64 + c4) =
                *(const int4*)(mask + (size_t)(b * SS + q0 + r) * SS + t0 + c4);
        }
        __syncthreads();

        // scores S[16 q][64 k] per warp
        float sc[8][4];
        #pragma unroll
        for (int i = 0; i < 8; i++)
            #pragma unroll
            for (int j = 0; j < 4; j++) sc[i][j] = 0.f;

        #pragma unroll
        for (int ks = 0; ks < 4; ks++) {
            uint32_t khf[8][2], klf[8][2];
            #pragma unroll
            for (int nt = 0; nt < 8; nt++) {
                uint32_t base = (uint32_t)(nt * 8 * LDF) * 2 + (uint32_t)(ks * 16) * 2 + b_off;
                ldm_x2(khf[nt][0], khf[nt][1], skh_b + base);
                ldm_x2(klf[nt][0], klf[nt][1], skl_b + base);
            }
            #pragma unroll
            for (int nt = 0; nt < 8; nt++) {
                mma16816(sc[nt], qhf[ks], khf[nt]);
                mma16816(sc[nt], qhf[ks], klf[nt]);
                mma16816(sc[nt], qlf[ks], khf[nt]);
            }
        }

        // mask + scale + row max
        float tmax0 = -INFINITY, tmax1 = -INFINITY;
        #pragma unroll
        for (int nt = 0; nt < 8; nt++) {
            int c = nt * 8 + (lane & 3) * 2;
            int2 mv0 = *(const int2*)&smsk[(w * 16 + lr0) * 64 + c];
            int2 mv1 = *(const int2*)&smsk[(w * 16 + lr0 + 8) * 64 + c];
            any0 |= mv0.x | mv0.y;
            any1 |= mv1.x | mv1.y;
            sc[nt][0] = mv0.x ? sc[nt][0] * 0.125f : -1e30f;
            sc[nt][1] = mv0.y ? sc[nt][1] * 0.125f : -1e30f;
            sc[nt][2] = mv1.x ? sc[nt][2] * 0.125f : -1e30f;
            sc[nt][3] = mv1.y ? sc[nt][3] * 0.125f : -1e30f;
            tmax0 = fmaxf(tmax0, fmaxf(sc[nt][0], sc[nt][1]));
            tmax1 = fmaxf(tmax1, fmaxf(sc[nt][2], sc[nt][3]));
        }
        tmax0 = fmaxf(tmax0, __shfl_xor_sync(0xffffffffu, tmax0, 1));
        tmax0 = fmaxf(tmax0, __shfl_xor_sync(0xffffffffu, tmax0, 2));
        tmax1 = fmaxf(tmax1, __shfl_xor_sync(0xffffffffu, tmax1, 1));
        tmax1 = fmaxf(tmax1, __shfl_xor_sync(0xffffffffu, tmax1, 2));

        float mn0 = fmaxf(m0, tmax0), mn1 = fmaxf(m1, tmax1);
        float corr0 = __expf(m0 - mn0), corr1 = __expf(m1 - mn1);
        m0 = mn0; m1 = mn1;

        float ps0 = 0.f, ps1 = 0.f;
        #pragma unroll
        for (int nt = 0; nt < 8; nt++) {
            sc[nt][0] = __expf(sc[nt][0] - mn0);
            sc[nt][1] = __expf(sc[nt][1] - mn0);
            sc[nt][2] = __expf(sc[nt][2] - mn1);
            sc[nt][3] = __expf(sc[nt][3] - mn1);
            ps0 += sc[nt][0] + sc[nt][1];
            ps1 += sc[nt][2] + sc[nt][3];
        }
        ps0 += __shfl_xor_sync(0xffffffffu, ps0, 1);
        ps0 += __shfl_xor_sync(0xffffffffu, ps0, 2);
        ps1 += __shfl_xor_sync(0xffffffffu, ps1, 1);
        ps1 += __shfl_xor_sync(0xffffffffu, ps1, 2);
        l0 = l0 * corr0 + ps0;
        l1 = l1 * corr1 + ps1;

        #pragma unroll
        for (int d = 0; d < 8; d++) {
            oacc[d][0] *= corr0; oacc[d][1] *= corr0;
            oacc[d][2] *= corr1; oacc[d][3] *= corr1;
        }

        // PV: per 16-key chunk kc
        #pragma unroll
        for (int kc = 0; kc < 4; kc++) {
            // P a-frags hi/lo from score frags 2kc, 2kc+1
            uint32_t pha[4], pla[4];
            {
                float p00 = sc[2*kc][0],   p01 = sc[2*kc][1];
                float p02 = sc[2*kc][2],   p03 = sc[2*kc][3];
                float p10 = sc[2*kc+1][0], p11 = sc[2*kc+1][1];
                float p12 = sc[2*kc+1][2], p13 = sc[2*kc+1][3];
                __nv_bfloat16 h;
                float r00, r01, r02, r03, r10, r11, r12, r13;
                h = __float2bfloat16(p00); r00 = p00 - __bfloat162float(h);
                h = __float2bfloat16(p01); r01 = p01 - __bfloat162float(h);
                h = __float2bfloat16(p02); r02 = p02 - __bfloat162float(h);
                h = __float2bfloat16(p03); r03 = p03 - __bfloat162float(h);
                h = __float2bfloat16(p10); r10 = p10 - __bfloat162float(h);
                h = __float2bfloat16(p11); r11 = p11 - __bfloat162float(h);
                h = __float2bfloat16(p12); r12 = p12 - __bfloat162float(h);
                h = __float2bfloat16(p13); r13 = p13 - __bfloat162float(h);
                pha[0] = pack2(p00, p01); pha[1] = pack2(p02, p03);
                pha[2] = pack2(p10, p11); pha[3] = pack2(p12, p13);
                pla[0] = pack2(r00, r01); pla[1] = pack2(r02, r03);
                pla[2] = pack2(r10, r11); pla[3] = pack2(r12, r13);
            }
            // V b-frags via ldmatrix.trans: rows = keys, cols = dims
            #pragma unroll
            for (int nt2 = 0; nt2 < 4; nt2++) {
                int key = kc * 16 + ((lane >> 3) & 1) * 8 + (lane & 7);
                int dimb = nt2 * 16 + (lane >> 4) * 8;
                uint32_t ad = (uint32_t)(key * LDF + dimb) * 2;
                uint32_t vh0, vh1, vh2, vh3, vl0, vl1, vl2, vl3;
                ldm_x4_t(vh0, vh1, vh2, vh3, svh_b + ad);
                ldm_x4_t(vl0, vl1, vl2, vl3, svl_b + ad);
                uint32_t bh0[2] = {vh0, vh1}, bh1[2] = {vh2, vh3};
                uint32_t bl0[2] = {vl0, vl1}, bl1[2] = {vl2, vl3};
                mma16816(oacc[nt2*2],     pha, bh0);
                mma16816(oacc[nt2*2],     pha, bl0);
                mma16816(oacc[nt2*2],     pla, bh0);
                mma16816(oacc[nt2*2 + 1], pha, bh1);
                mma16816(oacc[nt2*2 + 1], pha, bl1);
                mma16816(oacc[nt2*2 + 1], pla, bh1);
            }
        }
    }

    // finalize
    any0 |= __shfl_xor_sync(0xffffffffu, any0, 1);
    any0 |= __shfl_xor_sync(0xffffffffu, any0, 2);
    any1 |= __shfl_xor_sync(0xffffffffu, any1, 1);
    any1 |= __shfl_xor_sync(0xffffffffu, any1, 2);
    float inv0 = (any0 && l0 > 0.f) ? (1.0f / l0) : 0.0f;
    float inv1 = (any1 && l1 > 0.f) ? (1.0f / l1) : 0.0f;

    const int row0 = b * SS + q0 + w * 16 + lr0;
    #pragma unroll
    for (int nt = 0; nt < 8; nt++) {
        int col = h * HD + nt * 8 + (lane & 3) * 2;
        {
            float v0 = oacc[nt][0] * inv0, v1 = oacc[nt][1] * inv0;
            __nv_bfloat16 h0 = __float2bfloat16(v0), h1 = __float2bfloat16(v1);
            __nv_bfloat162 hp; hp.x = h0; hp.y = h1;
            __nv_bfloat162 lp;
            lp.x = __float2bfloat16(v0 - __bfloat162float(h0));
            lp.y = __float2bfloat16(v1 - __bfloat162float(h1));
            size_t o = (size_t)row0 * DD + col;
            *(__nv_bfloat162*)(Oh + o) = hp;
            *(__nv_bfloat162*)(Ol + o) = lp;
        }
        {
            float v0 = oacc[nt][2] * inv1, v1 = oacc[nt][3] * inv1;
            __nv_bfloat16 h0 = __float2bfloat16(v0), h1 = __float2bfloat16(v1);
            __nv_bfloat162 hp; hp.x = h0; hp.y = h1;
            __nv_bfloat162 lp;
            lp.x = __float2bfloat16(v0 - __bfloat162float(h0));
            lp.y = __float2bfloat16(v1 - __bfloat162float(h1));
            size_t o = (size_t)(row0 + 8) * DD + col;
            *(__nv_bfloat162*)(Oh + o) = hp;
            *(__nv_bfloat162*)(Ol + o) = lp;
        }
    }
}

// ---------------- launch ----------------
extern "C" void kernel_launch(void* const* d_in, const int* in_sizes, int n_in,
                              void* d_out, int out_size)
{
    const float* x      = (const float*)d_in[0];
    const int*   mask   = (const int*)d_in[1];
    const float* ln1_g  = (const float*)d_in[2];
    const float* ln1_b  = (const float*)d_in[3];
    const float* wq     = (const float*)d_in[4];
    const float* wk     = (const float*)d_in[5];
    const float* wv     = (const float*)d_in[6];
    const float* wo     = (const float*)d_in[7];
    const float* bo     = (const float*)d_in[8];
    const float* ln2_g  = (const float*)d_in[9];
    const float* ln2_b  = (const float*)d_in[10];
    const float* w1     = (const float*)d_in[11];
    const float* b1     = (const float*)d_in[12];
    const float* w2     = (const float*)d_in[13];
    const float* b2     = (const float*)d_in[14];
    float* out = (float*)d_out;

    __nv_bfloat16 *lnh, *lnl, *qh, *ql, *kh, *kl, *vh, *vl, *atth, *attl, *hh, *hl;
    __nv_bfloat16 *wqh, *wql, *wkh, *wkl, *wvh, *wvl, *woh, *wol, *w1h, *w1l, *w2h, *w2l;
    float *x1;
    cudaGetSymbolAddress((void**)&lnh,  g_lnh);  cudaGetSymbolAddress((void**)&lnl,  g_lnl);
    cudaGetSymbolAddress((void**)&qh,   g_qh);   cudaGetSymbolAddress((void**)&ql,   g_ql);
    cudaGetSymbolAddress((void**)&kh,   g_kh);   cudaGetSymbolAddress((void**)&kl,   g_kl);
    cudaGetSymbolAddress((void**)&vh,   g_vh);   cudaGetSymbolAddress((void**)&vl,   g_vl);
    cudaGetSymbolAddress((void**)&atth, g_atth); cudaGetSymbolAddress((void**)&attl, g_attl);
    cudaGetSymbolAddress((void**)&x1,   g_x1);
    cudaGetSymbolAddress((void**)&hh,   g_hh);   cudaGetSymbolAddress((void**)&hl,   g_hl);
    cudaGetSymbolAddress((void**)&wqh,  g_wqh);  cudaGetSymbolAddress((void**)&wql,  g_wql);
    cudaGetSymbolAddress((void**)&wkh,  g_wkh);  cudaGetSymbolAddress((void**)&wkl,  g_wkl);
    cudaGetSymbolAddress((void**)&wvh,  g_wvh);  cudaGetSymbolAddress((void**)&wvl,  g_wvl);
    cudaGetSymbolAddress((void**)&woh,  g_woh);  cudaGetSymbolAddress((void**)&wol,  g_wol);
    cudaGetSymbolAddress((void**)&w1h,  g_w1h);  cudaGetSymbolAddress((void**)&w1l,  g_w1l);
    cudaGetSymbolAddress((void**)&w2h,  g_w2h);  cudaGetSymbolAddress((void**)&w2l,  g_w2l);

    cudaFuncSetAttribute(mma_gemm,  cudaFuncAttributeMaxDynamicSharedMemorySize, SMEM_GEMM);
    cudaFuncSetAttribute(flash_mma, cudaFuncAttributeMaxDynamicSharedMemorySize, SMEM_FLASH);

    // 0) weight transpose + split (hi/lo bf16, [N,K])
    dim3 tb(32, 8);
    wprep_kernel<<<dim3(DD/32, DD/32), tb>>>(wq, wqh, wql, DD, DD);
    wprep_kernel<<<dim3(DD/32, DD/32), tb>>>(wk, wkh, wkl, DD, DD);
    wprep_kernel<<<dim3(DD/32, DD/32), tb>>>(wv, wvh, wvl, DD, DD);
    wprep_kernel<<<dim3(DD/32, DD/32), tb>>>(wo, woh, wol, DD, DD);
    wprep_kernel<<<dim3(FF/32, DD/32), tb>>>(w1, w1h, w1l, DD, FF);
    wprep_kernel<<<dim3(DD/32, FF/32), tb>>>(w2, w2h, w2l, FF, DD);

    // 1) LN1 -> split
    ln_kernel<<<ROWS, 256>>>(x, ln1_g, ln1_b, lnh, lnl);

    // 2) Q,K,V projections -> split bf16 outputs
    dim3 gQKV(DD/128, ROWS/128);
    mma_gemm<<<gQKV, 256, SMEM_GEMM>>>(lnh, lnl, wqh, wql, nullptr, nullptr, nullptr, qh, ql, ROWS, DD, DD, 0);
    mma_gemm<<<gQKV, 256, SMEM_GEMM>>>(lnh, lnl, wkh, wkl, nullptr, nullptr, nullptr, kh, kl, ROWS, DD, DD, 0);
    mma_gemm<<<gQKV, 256, SMEM_GEMM>>>(lnh, lnl, wvh, wvl, nullptr, nullptr, nullptr, vh, vl, ROWS, DD, DD, 0);

    // 3) attention (tensor cores) -> split output
    dim3 gF(SS/64, HH, BB);
    flash_mma<<<gF, 128, SMEM_FLASH>>>(qh, ql, kh, kl, vh, vl, mask, atth, attl);

    // 4) output projection + bias + residual -> x1 (fp32)
    mma_gemm<<<gQKV, 256, SMEM_GEMM>>>(atth, attl, woh, wol, bo, x, x1, nullptr, nullptr, ROWS, DD, DD, 0);

    // 5) LN2 -> split
    ln_kernel<<<ROWS, 256>>>(x1, ln2_g, ln2_b, lnh, lnl);

    // 6) MLP up + bias + gelu -> split h
    dim3 gM1(FF/128, ROWS/128);
    mma_gemm<<<gM1, 256, SMEM_GEMM>>>(lnh, lnl, w1h, w1l, b1, nullptr, nullptr, hh, hl, ROWS, FF, DD, 1);

    // 7) MLP down + bias + residual -> out
    dim3 gM2(DD/128, ROWS/128);
    mma_gemm<<<gM2, 256, SMEM_GEMM>>>(hh, hl, w2h, w2l, b2, x1, out, nullptr, nullptr, ROWS, DD, FF, 0);
}

// round 9
// speedup vs baseline: 2.8154x; 1.0413x over previous
#include <cuda_runtime.h>
#include <cuda_bf16.h>
#include <math.h>
#include <stdint.h>

// Problem constants
#define BB 4
#define SS 2048
#define DD 1024
#define HH 16
#define HD 64
#define FF 4096
#define ROWS (BB*SS)          // 8192
#define QKD 3072              // fused qkv width

// ---------------- scratch (device globals; no allocation) ----------------
__device__ __nv_bfloat16 g_lnh[(size_t)ROWS * DD];
__device__ __nv_bfloat16 g_lnl[(size_t)ROWS * DD];
__device__ __nv_bfloat16 g_qkvh[(size_t)ROWS * QKD], g_qkvl[(size_t)ROWS * QKD];
__device__ __nv_bfloat16 g_atth[(size_t)ROWS * DD];
__device__ __nv_bfloat16 g_attl[(size_t)ROWS * DD];
__device__ float g_x1[(size_t)ROWS * DD];
__device__ __nv_bfloat16 g_hh[(size_t)ROWS * FF];
__device__ __nv_bfloat16 g_hl[(size_t)ROWS * FF];
// transposed + split weights: wt[N][K]
__device__ __nv_bfloat16 g_wqkvh[(size_t)QKD*DD], g_wqkvl[(size_t)QKD*DD];
__device__ __nv_bfloat16 g_woh[(size_t)DD*DD], g_wol[(size_t)DD*DD];
__device__ __nv_bfloat16 g_w1h[(size_t)DD*FF], g_w1l[(size_t)DD*FF];
__device__ __nv_bfloat16 g_w2h[(size_t)FF*DD], g_w2l[(size_t)FF*DD];

// ---------------- helpers ----------------
__device__ __forceinline__ uint32_t smem_u32(const void* p) {
    uint32_t a;
    asm("{ .reg .u64 t; cvta.to.shared.u64 t, %1; cvt.u32.u64 %0, t; }" : "=r"(a) : "l"(p));
    return a;
}
__device__ __forceinline__ void ldm_x4(uint32_t& r0, uint32_t& r1, uint32_t& r2, uint32_t& r3, uint32_t a) {
    asm volatile("ldmatrix.sync.aligned.m8n8.x4.shared.b16 {%0,%1,%2,%3}, [%4];"
                 : "=r"(r0), "=r"(r1), "=r"(r2), "=r"(r3) : "r"(a));
}
__device__ __forceinline__ void ldm_x4_t(uint32_t& r0, uint32_t& r1, uint32_t& r2, uint32_t& r3, uint32_t a) {
    asm volatile("ldmatrix.sync.aligned.m8n8.x4.trans.shared.b16 {%0,%1,%2,%3}, [%4];"
                 : "=r"(r0), "=r"(r1), "=r"(r2), "=r"(r3) : "r"(a));
}
__device__ __forceinline__ void ldm_x2(uint32_t& r0, uint32_t& r1, uint32_t a) {
    asm volatile("ldmatrix.sync.aligned.m8n8.x2.shared.b16 {%0,%1}, [%2];"
                 : "=r"(r0), "=r"(r1) : "r"(a));
}
__device__ __forceinline__ void mma16816(float* c, const uint32_t* a, const uint32_t* b) {
    asm volatile("mma.sync.aligned.m16n8k16.row.col.f32.bf16.bf16.f32 "
                 "{%0,%1,%2,%3}, {%4,%5,%6,%7}, {%8,%9}, {%0,%1,%2,%3};"
                 : "+f"(c[0]), "+f"(c[1]), "+f"(c[2]), "+f"(c[3])
                 : "r"(a[0]), "r"(a[1]), "r"(a[2]), "r"(a[3]), "r"(b[0]), "r"(b[1]));
}
__device__ __forceinline__ uint32_t pack2(float a, float b) {
    __nv_bfloat162 t = __floats2bfloat162_rn(a, b);
    return *(uint32_t*)&t;
}
#define CP_ASYNC16(dst, src) asm volatile("cp.async.cg.shared.global [%0], [%1], 16;" :: "r"(dst), "l"(src))
#define CP_COMMIT()  asm volatile("cp.async.commit_group;")
#define CP_WAIT0()   asm volatile("cp.async.wait_group 0;")
#define CP_WAIT1()   asm volatile("cp.async.wait_group 1;")

// ---------------- LayerNorm -> split bf16 hi/lo ----------------
__global__ void ln_kernel(const float* __restrict__ x,
                          const float* __restrict__ g,
                          const float* __restrict__ b,
                          __nv_bfloat16* __restrict__ oh,
                          __nv_bfloat16* __restrict__ ol)
{
    const int row = blockIdx.x;
    const float* xr = x + (size_t)row * DD;

    float s = 0.f, s2 = 0.f;
    for (int i = threadIdx.x; i < DD; i += blockDim.x) {
        float v = xr[i];
        s += v; s2 += v * v;
    }
    __shared__ float red[64];
    for (int o = 16; o; o >>= 1) {
        s  += __shfl_xor_sync(0xffffffffu, s,  o);
        s2 += __shfl_xor_sync(0xffffffffu, s2, o);
    }
    int wid = threadIdx.x >> 5, lid = threadIdx.x & 31;
    if (lid == 0) { red[wid] = s; red[wid + 32] = s2; }
    __syncthreads();
    if (wid == 0) {
        int nw = blockDim.x >> 5;
        s  = (lid < nw) ? red[lid] : 0.f;
        s2 = (lid < nw) ? red[lid + 32] : 0.f;
        for (int o = 16; o; o >>= 1) {
            s  += __shfl_xor_sync(0xffffffffu, s,  o);
            s2 += __shfl_xor_sync(0xffffffffu, s2, o);
        }
        if (lid == 0) { red[0] = s; red[1] = s2; }
    }
    __syncthreads();
    float mean = red[0] * (1.0f / DD);
    float var  = red[1] * (1.0f / DD) - mean * mean;
    float inv  = rsqrtf(var + 1e-5f);
    for (int i = threadIdx.x; i < DD; i += blockDim.x) {
        float v = (xr[i] - mean) * inv * g[i] + b[i];
        __nv_bfloat16 h = __float2bfloat16(v);
        oh[(size_t)row * DD + i] = h;
        ol[(size_t)row * DD + i] = __float2bfloat16(v - __bfloat162float(h));
    }
}

// ---------------- weight transpose + split: w[K,N] -> th/tl[N,K] ----------
__global__ void wprep_kernel(const float* __restrict__ w,
                             __nv_bfloat16* __restrict__ th,
                             __nv_bfloat16* __restrict__ tl, int K, int N)
{
    __shared__ float t[32][33];
    int nx0 = blockIdx.x * 32, ky0 = blockIdx.y * 32;
    int tx = threadIdx.x, ty = threadIdx.y;   // 32 x 8
    #pragma unroll
    for (int d = 0; d < 4; d++)
        t[ty + d * 8][tx] = w[(size_t)(ky0 + ty + d * 8) * N + nx0 + tx];
    __syncthreads();
    #pragma unroll
    for (int d = 0; d < 4; d++) {
        float v = t[tx][ty + d * 8];
        __nv_bfloat16 h = __float2bfloat16(v);
        size_t o = (size_t)(nx0 + ty + d * 8) * K + ky0 + tx;
        th[o] = h;
        tl[o] = __float2bfloat16(v - __bfloat162float(h));
    }
}

// ---------------- mma.sync split-bf16 GEMM, cp.async 3-stage --------------
// C[M,N] = (Ah+Al)[M,K] @ (Bh+Bl)[N,K]^T, fp32 accum.
// CTA tile 128x128, BK=32, 256 threads (8 warps 2m x 4n, warp tile 64x32).
#define LDT 40                    // smem row stride (32 + 8 pad) -> 80B
#define GARR (128*LDT*2)          // 10240 B per array
#define GSTG (4*GARR)             // 40960 B per stage
#define SMEM_GEMM (3*GSTG)        // 122880 B

__global__ void __launch_bounds__(256, 1)
mma_gemm(const __nv_bfloat16* __restrict__ Ah, const __nv_bfloat16* __restrict__ Al,
         const __nv_bfloat16* __restrict__ Bh, const __nv_bfloat16* __restrict__ Bl,
         const float* __restrict__ bias, const float* __restrict__ resid,
         float* __restrict__ Cf, __nv_bfloat16* __restrict__ Ch,
         __nv_bfloat16* __restrict__ Cl, int M, int N, int K, int dogelu)
{
    extern __shared__ char gsm[];
    const uint32_t sb = smem_u32(gsm);

    const int tid = threadIdx.x, lane = tid & 31, wid = tid >> 5;
    const int wm = wid & 1, wn = wid >> 1;           // warp 64m x 32n
    const int bm = blockIdx.y * 128, bn = blockIdx.x * 128;

    float acc[4][4][4];
    #pragma unroll
    for (int i = 0; i < 4; i++)
        #pragma unroll
        for (int j = 0; j < 4; j++)
            #pragma unroll
            for (int r = 0; r < 4; r++) acc[i][j][r] = 0.f;

    const int l_r0 = tid >> 2, l_c8 = (tid & 3) * 8;
    const uint32_t a_off = (uint32_t)((lane & 15) * LDT + (lane >> 4) * 8) * 2;
    const uint32_t b_off = (uint32_t)((lane & 7) * LDT + ((lane >> 3) & 1) * 8) * 2;

    const int T = K >> 5;

    // prologue: stages 0, 1
    #pragma unroll
    for (int p = 0; p < 2; p++) {
        const int kn = p << 5;
        const uint32_t st = (uint32_t)p * GSTG;
        #pragma unroll
        for (int u = 0; u < 2; u++) {
            int r = l_r0 + u * 64;
            uint32_t so = st + (uint32_t)(r * LDT + l_c8) * 2;
            size_t ga = (size_t)(bm + r) * K + kn + l_c8;
            size_t gb = (size_t)(bn + r) * K + kn + l_c8;
            CP_ASYNC16(sb + 0*GARR + so, Ah + ga);
            CP_ASYNC16(sb + 1*GARR + so, Al + ga);
            CP_ASYNC16(sb + 2*GARR + so, Bh + gb);
            CP_ASYNC16(sb + 3*GARR + so, Bl + gb);
        }
        CP_COMMIT();
    }

    for (int t = 0; t < T; t++) {
        if (t + 1 < T) { CP_WAIT1(); } else { CP_WAIT0(); }
        __syncthreads();

        const uint32_t st = (uint32_t)(t % 3) * GSTG;
        const uint32_t sAh_b = sb + st, sAl_b = sb + st + GARR;
        const uint32_t sBh_b = sb + st + 2*GARR, sBl_b = sb + st + 3*GARR;

        #pragma unroll
        for (int ks = 0; ks < 2; ks++) {
            const uint32_t kso = ks * 16 * 2;
            uint32_t ah[4][4], al[4][4], bh[4][2], bl[4][2];
            #pragma unroll
            for (int mt = 0; mt < 4; mt++) {
                uint32_t base = (uint32_t)((wm * 64 + mt * 16) * LDT) * 2 + kso + a_off;
                ldm_x4(ah[mt][0], ah[mt][1], ah[mt][2], ah[mt][3], sAh_b + base);
                ldm_x4(al[mt][0], al[mt][1], al[mt][2], al[mt][3], sAl_b + base);
            }
            #pragma unroll
            for (int nt = 0; nt < 4; nt++) {
                uint32_t base = (uint32_t)((wn * 32 + nt * 8) * LDT) * 2 + kso + b_off;
                ldm_x2(bh[nt][0], bh[nt][1], sBh_b + base);
                ldm_x2(bl[nt][0], bl[nt][1], sBl_b + base);
            }
            #pragma unroll
            for (int mt = 0; mt < 4; mt++)
                #pragma unroll
                for (int nt = 0; nt < 4; nt++) {
                    mma16816(acc[mt][nt], ah[mt], bh[nt]);
                    mma16816(acc[mt][nt], ah[mt], bl[nt]);
                    mma16816(acc[mt][nt], al[mt], bh[nt]);
                }
        }
        __syncthreads();

        if (t + 2 < T) {
            const int kn = (t + 2) << 5;
            const uint32_t sti = (uint32_t)((t + 2) % 3) * GSTG;
            #pragma unroll
            for (int u = 0; u < 2; u++) {
                int r = l_r0 + u * 64;
                uint32_t so = sti + (uint32_t)(r * LDT + l_c8) * 2;
                size_t ga = (size_t)(bm + r) * K + kn + l_c8;
                size_t gb = (size_t)(bn + r) * K + kn + l_c8;
                CP_ASYNC16(sb + 0*GARR + so, Ah + ga);
                CP_ASYNC16(sb + 1*GARR + so, Al + ga);
                CP_ASYNC16(sb + 2*GARR + so, Bh + gb);
                CP_ASYNC16(sb + 3*GARR + so, Bl + gb);
            }
            CP_COMMIT();
        }
    }

    // epilogue
    const int mrow = bm + wm * 64 + (lane >> 2);
    const int ncol = bn + wn * 32 + (lane & 3) * 2;
    #pragma unroll
    for (int mt = 0; mt < 4; mt++) {
        #pragma unroll
        for (int half = 0; half < 2; half++) {
            int row = mrow + mt * 16 + half * 8;
            #pragma unroll
            for (int nt = 0; nt < 4; nt++) {
                int col = ncol + nt * 8;
                float v0 = acc[mt][nt][half * 2 + 0];
                float v1 = acc[mt][nt][half * 2 + 1];
                if (bias) { v0 += __ldg(bias + col); v1 += __ldg(bias + col + 1); }
                if (dogelu) {
                    v0 = 0.5f * v0 * (1.0f + erff(v0 * 0.70710678118654752f));
                    v1 = 0.5f * v1 * (1.0f + erff(v1 * 0.70710678118654752f));
                }
                size_t o = (size_t)row * N + col;
                if (resid) { v0 += resid[o]; v1 += resid[o + 1]; }
                if (Cf) { *(float2*)(Cf + o) = make_float2(v0, v1); }
                if (Ch) {
                    __nv_bfloat16 h0 = __float2bfloat16(v0);
                    __nv_bfloat16 h1 = __float2bfloat16(v1);
                    __nv_bfloat162 hp; hp.x = h0; hp.y = h1;
                    __nv_bfloat162 lp;
                    lp.x = __float2bfloat16(v0 - __bfloat162float(h0));
                    lp.y = __float2bfloat16(v1 - __bfloat162float(h1));
                    *(__nv_bfloat162*)(Ch + o) = hp;
                    *(__nv_bfloat162*)(Cl + o) = lp;
                }
            }
        }
    }
}

// ---------------- Flash attention, mma.sync split-bf16, pipelined --------
// CTA: 256 threads (8 warps), 128 q-rows x one head, 64-key tiles,
// 2-stage cp.async pipeline for K/V/mask. Reads fused qkv buffers.
#define LDF 72
#define FQH 0
#define FQL 18432
#define FKV 36864                 // 4 arrays x 9216 per stage, 2 stages
#define KVSTG 36864
#define FMK (FKV + 2*KVSTG)       // 110592; 2 x 32768
#define MKSTG 32768
#define SMEM_FLASH (FMK + 2*MKSTG)   // 176128

__global__ void __launch_bounds__(256, 1)
flash_mma(const __nv_bfloat16* __restrict__ qkvh, const __nv_bfloat16* __restrict__ qkvl,
          const int* __restrict__ mask,
          __nv_bfloat16* __restrict__ Oh, __nv_bfloat16* __restrict__ Ol)
{
    extern __shared__ char fsm[];
    const uint32_t sb = smem_u32(fsm);

    const int b = blockIdx.z, h = blockIdx.y;
    const int q0 = blockIdx.x * 128;
    const int tid = threadIdx.x, lane = tid & 31, w = tid >> 5;

    // ---- prologue: Q tile (group 0), KV+mask tile 0 (group 1) ----
    #pragma unroll
    for (int j = 0; j < 4; j++) {
        int e = tid + j * 256;           // 1024 chunks
        int r = e >> 3, c8 = (e & 7) * 8;
        size_t gq = (size_t)(b * SS + q0 + r) * QKD + h * HD + c8;
        uint32_t so = (uint32_t)(r * LDF + c8) * 2;
        CP_ASYNC16(sb + FQH + so, qkvh + gq);
        CP_ASYNC16(sb + FQL + so, qkvl + gq);
    }
    CP_COMMIT();
    {
        const uint32_t kvb = sb + FKV, mkb = sb + FMK;
        #pragma unroll
        for (int j = 0; j < 2; j++) {
            int e = tid + j * 256;       // 512 chunks
            int r = e >> 3, c8 = (e & 7) * 8;
            size_t gk = (size_t)(b * SS + r) * QKD + DD + h * HD + c8;
            uint32_t so = (uint32_t)(r * LDF + c8) * 2;
            CP_ASYNC16(kvb + 0*9216  + so, qkvh + gk);
            CP_ASYNC16(kvb + 1*9216  + so, qkvl + gk);
            CP_ASYNC16(kvb + 2*9216  + so, qkvh + gk + DD);
            CP_ASYNC16(kvb + 3*9216  + so, qkvl + gk + DD);
        }
        #pragma unroll
        for (int j = 0; j < 8; j++) {
            int e = tid + j * 256;       // 2048 int4
            int r = e >> 4, c4 = (e & 15) * 4;
            CP_ASYNC16(mkb + (uint32_t)(r * 64 + c4) * 4,
                       mask + (size_t)(b * SS + q0 + r) * SS + c4);
        }
        CP_COMMIT();
    }

    CP_WAIT1();           // Q ready (tile0 may still be in flight)
    __syncthreads();

    const uint32_t a_off = (uint32_t)((lane & 15) * LDF + (lane >> 4) * 8) * 2;
    const uint32_t b_off = (uint32_t)((lane & 7) * LDF + ((lane >> 3) & 1) * 8) * 2;

    uint32_t qhf[4][4], qlf[4][4];
    #pragma unroll
    for (int ks = 0; ks < 4; ks++) {
        uint32_t base = (uint32_t)(w * 16 * LDF) * 2 + (uint32_t)(ks * 16) * 2 + a_off;
        ldm_x4(qhf[ks][0], qhf[ks][1], qhf[ks][2], qhf[ks][3], sb + FQH + base);
        ldm_x4(qlf[ks][0], qlf[ks][1], qlf[ks][2], qlf[ks][3], sb + FQL + base);
    }

    float oacc[8][4];
    #pragma unroll
    for (int i = 0; i < 8; i++)
        #pragma unroll
        for (int j = 0; j < 4; j++) oacc[i][j] = 0.f;
    float m0 = -INFINITY, m1 = -INFINITY, l0 = 0.f, l1 = 0.f;
    int any0 = 0, any1 = 0;
    const int lr0 = lane >> 2;

    const int T = SS / 64;
    for (int t = 0; t < T; t++) {
        // prefetch tile t+1 into stage (t+1)&1
        if (t + 1 < T) {
            const int t0n = (t + 1) * 64;
            const uint32_t kvb = sb + FKV + (uint32_t)((t + 1) & 1) * KVSTG;
            const uint32_t mkb = sb + FMK + (uint32_t)((t + 1) & 1) * MKSTG;
            #pragma unroll
            for (int j = 0; j < 2; j++) {
                int e = tid + j * 256;
                int r = e >> 3, c8 = (e & 7) * 8;
                size_t gk = (size_t)(b * SS + t0n + r) * QKD + DD + h * HD + c8;
                uint32_t so = (uint32_t)(r * LDF + c8) * 2;
                CP_ASYNC16(kvb + 0*9216 + so, qkvh + gk);
                CP_ASYNC16(kvb + 1*9216 + so, qkvl + gk);
                CP_ASYNC16(kvb + 2*9216 + so, qkvh + gk + DD);
                CP_ASYNC16(kvb + 3*9216 + so, qkvl + gk + DD);
            }
            #pragma unroll
            for (int j = 0; j < 8; j++) {
                int e = tid + j * 256;
                int r = e >> 4, c4 = (e & 15) * 4;
                CP_ASYNC16(mkb + (uint32_t)(r * 64 + c4) * 4,
                           mask + (size_t)(b * SS + q0 + r) * SS + t0n + c4);
            }
            CP_COMMIT();
            CP_WAIT1();
        } else {
            CP_WAIT0();
        }
        __syncthreads();

        const uint32_t kvb = sb + FKV + (uint32_t)(t & 1) * KVSTG;
        const uint32_t skh_b = kvb, skl_b = kvb + 9216;
        const uint32_t svh_b = kvb + 18432, svl_b = kvb + 27648;
        const int* smsk = (const int*)(fsm + FMK + (size_t)(t & 1) * MKSTG);

        // scores S[16 q][64 k] per warp
        float sc[8][4];
        #pragma unroll
        for (int i = 0; i < 8; i++)
            #pragma unroll
            for (int j = 0; j < 4; j++) sc[i][j] = 0.f;

        #pragma unroll
        for (int ks = 0; ks < 4; ks++) {
            uint32_t khf[8][2], klf[8][2];
            #pragma unroll
            for (int nt = 0; nt < 8; nt++) {
                uint32_t base = (uint32_t)(nt * 8 * LDF) * 2 + (uint32_t)(ks * 16) * 2 + b_off;
                ldm_x2(khf[nt][0], khf[nt][1], skh_b + base);
                ldm_x2(klf[nt][0], klf[nt][1], skl_b + base);
            }
            #pragma unroll
            for (int nt = 0; nt < 8; nt++) {
                mma16816(sc[nt], qhf[ks], khf[nt]);
                mma16816(sc[nt], qhf[ks], klf[nt]);
                mma16816(sc[nt], qlf[ks], khf[nt]);
            }
        }

        // mask + scale + row max
        float tmax0 = -INFINITY, tmax1 = -INFINITY;
        #pragma unroll
        for (int nt = 0; nt < 8; nt++) {
            int c = nt * 8 + (lane & 3) * 2;
            int2 mv0 = *(const int2*)&smsk[(w * 16 + lr0) * 64 + c];
            int2 mv1 = *(const int2*)&smsk[(w * 16 + lr0 + 8) * 64 + c];
            any0 |= mv0.x | mv0.y;
            any1 |= mv1.x | mv1.y;
            sc[nt][0] = mv0.x ? sc[nt][0] * 0.125f : -1e30f;
            sc[nt][1] = mv0.y ? sc[nt][1] * 0.125f : -1e30f;
            sc[nt][2] = mv1.x ? sc[nt][2] * 0.125f : -1e30f;
            sc[nt][3] = mv1.y ? sc[nt][3] * 0.125f : -1e30f;
            tmax0 = fmaxf(tmax0, fmaxf(sc[nt][0], sc[nt][1]));
            tmax1 = fmaxf(tmax1, fmaxf(sc[nt][2], sc[nt][3]));
        }
        tmax0 = fmaxf(tmax0, __shfl_xor_sync(0xffffffffu, tmax0, 1));
        tmax0 = fmaxf(tmax0, __shfl_xor_sync(0xffffffffu, tmax0, 2));
        tmax1 = fmaxf(tmax1, __shfl_xor_sync(0xffffffffu, tmax1, 1));
        tmax1 = fmaxf(tmax1, __shfl_xor_sync(0xffffffffu, tmax1, 2));

        float mn0 = fmaxf(m0, tmax0), mn1 = fmaxf(m1, tmax1);
        float corr0 = __expf(m0 - mn0), corr1 = __expf(m1 - mn1);
        m0 = mn0; m1 = mn1;

        float ps0 = 0.f, ps1 = 0.f;
        #pragma unroll
        for (int nt = 0; nt < 8; nt++) {
            sc[nt][0] = __expf(sc[nt][0] - mn0);
            sc[nt][1] = __expf(sc[nt][1] - mn0);
            sc[nt][2] = __expf(sc[nt][2] - mn1);
            sc[nt][3] = __expf(sc[nt][3] - mn1);
            ps0 += sc[nt][0] + sc[nt][1];
            ps1 += sc[nt][2] + sc[nt][3];
        }
        ps0 += __shfl_xor_sync(0xffffffffu, ps0, 1);
        ps0 += __shfl_xor_sync(0xffffffffu, ps0, 2);
        ps1 += __shfl_xor_sync(0xffffffffu, ps1, 1);
        ps1 += __shfl_xor_sync(0xffffffffu, ps1, 2);
        l0 = l0 * corr0 + ps0;
        l1 = l1 * corr1 + ps1;

        #pragma unroll
        for (int d = 0; d < 8; d++) {
            oacc[d][0] *= corr0; oacc[d][1] *= corr0;
            oacc[d][2] *= corr1; oacc[d][3] *= corr1;
        }

        // PV
        #pragma unroll
        for (int kc = 0; kc < 4; kc++) {
            uint32_t pha[4], pla[4];
            {
                float p00 = sc[2*kc][0],   p01 = sc[2*kc][1];
                float p02 = sc[2*kc][2],   p03 = sc[2*kc][3];
                float p10 = sc[2*kc+1][0], p11 = sc[2*kc+1][1];
                float p12 = sc[2*kc+1][2], p13 = sc[2*kc+1][3];
                __nv_bfloat16 hh;
                float r00, r01, r02, r03, r10, r11, r12, r13;
                hh = __float2bfloat16(p00); r00 = p00 - __bfloat162float(hh);
                hh = __float2bfloat16(p01); r01 = p01 - __bfloat162float(hh);
                hh = __float2bfloat16(p02); r02 = p02 - __bfloat162float(hh);
                hh = __float2bfloat16(p03); r03 = p03 - __bfloat162float(hh);
                hh = __float2bfloat16(p10); r10 = p10 - __bfloat162float(hh);
                hh = __float2bfloat16(p11); r11 = p11 - __bfloat162float(hh);
                hh = __float2bfloat16(p12); r12 = p12 - __bfloat162float(hh);
                hh = __float2bfloat16(p13); r13 = p13 - __bfloat162float(hh);
                pha[0] = pack2(p00, p01); pha[1] = pack2(p02, p03);
                pha[2] = pack2(p10, p11); pha[3] = pack2(p12, p13);
                pla[0] = pack2(r00, r01); pla[1] = pack2(r02, r03);
                pla[2] = pack2(r10, r11); pla[3] = pack2(r12, r13);
            }
            #pragma unroll
            for (int nt2 = 0; nt2 < 4; nt2++) {
                int key = kc * 16 + ((lane >> 3) & 1) * 8 + (lane & 7);
                int dimb = nt2 * 16 + (lane >> 4) * 8;
                uint32_t ad = (uint32_t)(key * LDF + dimb) * 2;
                uint32_t vh0, vh1, vh2, vh3, vl0, vl1, vl2, vl3;
                ldm_x4_t(vh0, vh1, vh2, vh3, svh_b + ad);
                ldm_x4_t(vl0, vl1, vl2, vl3, svl_b + ad);
                uint32_t bh0[2] = {vh0, vh1}, bh1[2] = {vh2, vh3};
                uint32_t bl0[2] = {vl0, vl1}, bl1[2] = {vl2, vl3};
                mma16816(oacc[nt2*2],     pha, bh0);
                mma16816(oacc[nt2*2],     pha, bl0);
                mma16816(oacc[nt2*2],     pla, bh0);
                mma16816(oacc[nt2*2 + 1], pha, bh1);
                mma16816(oacc[nt2*2 + 1], pha, bl1);
                mma16816(oacc[nt2*2 + 1], pla, bh1);
            }
        }
        __syncthreads();
    }

    // finalize
    any0 |= __shfl_xor_sync(0xffffffffu, any0, 1);
    any0 |= __shfl_xor_sync(0xffffffffu, any0, 2);
    any1 |= __shfl_xor_sync(0xffffffffu, any1, 1);
    any1 |= __shfl_xor_sync(0xffffffffu, any1, 2);
    float inv0 = (any0 && l0 > 0.f) ? (1.0f / l0) : 0.0f;
    float inv1 = (any1 && l1 > 0.f) ? (1.0f / l1) : 0.0f;

    const int row0 = b * SS + q0 + w * 16 + lr0;
    #pragma unroll
    for (int nt = 0; nt < 8; nt++) {
        int col = h * HD + nt * 8 + (lane & 3) * 2;
        {
            float v0 = oacc[nt][0] * inv0, v1 = oacc[nt][1] * inv0;
            __nv_bfloat16 h0 = __float2bfloat16(v0), h1 = __float2bfloat16(v1);
            __nv_bfloat162 hp; hp.x = h0; hp.y = h1;
            __nv_bfloat162 lp;
            lp.x = __float2bfloat16(v0 - __bfloat162float(h0));
            lp.y = __float2bfloat16(v1 - __bfloat162float(h1));
            size_t o = (size_t)row0 * DD + col;
            *(__nv_bfloat162*)(Oh + o) = hp;
            *(__nv_bfloat162*)(Ol + o) = lp;
        }
        {
            float v0 = oacc[nt][2] * inv1, v1 = oacc[nt][3] * inv1;
            __nv_bfloat16 h0 = __float2bfloat16(v0), h1 = __float2bfloat16(v1);
            __nv_bfloat162 hp; hp.x = h0; hp.y = h1;
            __nv_bfloat162 lp;
            lp.x = __float2bfloat16(v0 - __bfloat162float(h0));
            lp.y = __float2bfloat16(v1 - __bfloat162float(h1));
            size_t o = (size_t)(row0 + 8) * DD + col;
            *(__nv_bfloat162*)(Oh + o) = hp;
            *(__nv_bfloat162*)(Ol + o) = lp;
        }
    }
}

// ---------------- launch ----------------
extern "C" void kernel_launch(void* const* d_in, const int* in_sizes, int n_in,
                              void* d_out, int out_size)
{
    const float* x      = (const float*)d_in[0];
    const int*   mask   = (const int*)d_in[1];
    const float* ln1_g  = (const float*)d_in[2];
    const float* ln1_b  = (const float*)d_in[3];
    const float* wq     = (const float*)d_in[4];
    const float* wk     = (const float*)d_in[5];
    const float* wv     = (const float*)d_in[6];
    const float* wo     = (const float*)d_in[7];
    const float* bo     = (const float*)d_in[8];
    const float* ln2_g  = (const float*)d_in[9];
    const float* ln2_b  = (const float*)d_in[10];
    const float* w1     = (const float*)d_in[11];
    const float* b1     = (const float*)d_in[12];
    const float* w2     = (const float*)d_in[13];
    const float* b2     = (const float*)d_in[14];
    float* out = (float*)d_out;

    __nv_bfloat16 *lnh, *lnl, *qkvh, *qkvl, *atth, *attl, *hh, *hl;
    __nv_bfloat16 *wqkvh, *wqkvl, *woh, *wol, *w1h, *w1l, *w2h, *w2l;
    float *x1;
    cudaGetSymbolAddress((void**)&lnh,   g_lnh);   cudaGetSymbolAddress((void**)&lnl,   g_lnl);
    cudaGetSymbolAddress((void**)&qkvh,  g_qkvh);  cudaGetSymbolAddress((void**)&qkvl,  g_qkvl);
    cudaGetSymbolAddress((void**)&atth,  g_atth);  cudaGetSymbolAddress((void**)&attl,  g_attl);
    cudaGetSymbolAddress((void**)&x1,    g_x1);
    cudaGetSymbolAddress((void**)&hh,    g_hh);    cudaGetSymbolAddress((void**)&hl,    g_hl);
    cudaGetSymbolAddress((void**)&wqkvh, g_wqkvh); cudaGetSymbolAddress((void**)&wqkvl, g_wqkvl);
    cudaGetSymbolAddress((void**)&woh,   g_woh);   cudaGetSymbolAddress((void**)&wol,   g_wol);
    cudaGetSymbolAddress((void**)&w1h,   g_w1h);   cudaGetSymbolAddress((void**)&w1l,   g_w1l);
    cudaGetSymbolAddress((void**)&w2h,   g_w2h);   cudaGetSymbolAddress((void**)&w2l,   g_w2l);

    cudaFuncSetAttribute(mma_gemm,  cudaFuncAttributeMaxDynamicSharedMemorySize, SMEM_GEMM);
    cudaFuncSetAttribute(flash_mma, cudaFuncAttributeMaxDynamicSharedMemorySize, SMEM_FLASH);

    // 0) weight transpose + split; q/k/v concatenated along N in wqkv
    dim3 tb(32, 8);
    wprep_kernel<<<dim3(DD/32, DD/32), tb>>>(wq, wqkvh,                     wqkvl,                     DD, DD);
    wprep_kernel<<<dim3(DD/32, DD/32), tb>>>(wk, wqkvh + (size_t)DD*DD,     wqkvl + (size_t)DD*DD,     DD, DD);
    wprep_kernel<<<dim3(DD/32, DD/32), tb>>>(wv, wqkvh + (size_t)2*DD*DD,   wqkvl + (size_t)2*DD*DD,   DD, DD);
    wprep_kernel<<<dim3(DD/32, DD/32), tb>>>(wo, woh, wol, DD, DD);
    wprep_kernel<<<dim3(FF/32, DD/32), tb>>>(w1, w1h, w1l, DD, FF);
    wprep_kernel<<<dim3(DD/32, FF/32), tb>>>(w2, w2h, w2l, FF, DD);

    // 1) LN1 -> split
    ln_kernel<<<ROWS, 256>>>(x, ln1_g, ln1_b, lnh, lnl);

    // 2) fused QKV projection -> qkv split buffers [ROWS][3072]
    dim3 gQKV(QKD/128, ROWS/128);
    mma_gemm<<<gQKV, 256, SMEM_GEMM>>>(lnh, lnl, wqkvh, wqkvl, nullptr, nullptr,
                                       nullptr, qkvh, qkvl, ROWS, QKD, DD, 0);

    // 3) attention (tensor cores, pipelined) -> split output
    dim3 gF(SS/128, HH, BB);
    flash_mma<<<gF, 256, SMEM_FLASH>>>(qkvh, qkvl, mask, atth, attl);

    // 4) output projection + bias + residual -> x1 (fp32)
    dim3 gO(DD/128, ROWS/128);
    mma_gemm<<<gO, 256, SMEM_GEMM>>>(atth, attl, woh, wol, bo, x, x1, nullptr, nullptr, ROWS, DD, DD, 0);

    // 5) LN2 -> split
    ln_kernel<<<ROWS, 256>>>(x1, ln2_g, ln2_b, lnh, lnl);

    // 6) MLP up + bias + gelu -> split h
    dim3 gM1(FF/128, ROWS/128);
    mma_gemm<<<gM1, 256, SMEM_GEMM>>>(lnh, lnl, w1h, w1l, b1, nullptr, nullptr, hh, hl, ROWS, FF, DD, 1);

    // 7) MLP down + bias + residual -> out
    dim3 gM2(DD/128, ROWS/128);
    mma_gemm<<<gM2, 256, SMEM_GEMM>>>(hh, hl, w2h, w2l, b2, x1, out, nullptr, nullptr, ROWS, DD, FF, 0);
}

// round 10
// speedup vs baseline: 2.8650x; 1.0176x over previous
#include <cuda_runtime.h>
#include <cuda_bf16.h>
#include <math.h>
#include <stdint.h>

// Problem constants
#define BB 4
#define SS 2048
#define DD 1024
#define HH 16
#define HD 64
#define FF 4096
#define ROWS (BB*SS)          // 8192
#define QKD 3072              // fused qkv width

// ---------------- scratch (device globals; no allocation) ----------------
__device__ __nv_bfloat16 g_lnh[(size_t)ROWS * DD];
__device__ __nv_bfloat16 g_lnl[(size_t)ROWS * DD];
__device__ __nv_bfloat16 g_qkvh[(size_t)ROWS * QKD], g_qkvl[(size_t)ROWS * QKD];
__device__ __nv_bfloat16 g_atth[(size_t)ROWS * DD];
__device__ __nv_bfloat16 g_attl[(size_t)ROWS * DD];
__device__ float g_x1[(size_t)ROWS * DD];
__device__ __nv_bfloat16 g_hh[(size_t)ROWS * FF];
__device__ __nv_bfloat16 g_hl[(size_t)ROWS * FF];
// transposed + split weights: wt[N][K]
__device__ __nv_bfloat16 g_wqkvh[(size_t)QKD*DD], g_wqkvl[(size_t)QKD*DD];
__device__ __nv_bfloat16 g_woh[(size_t)DD*DD], g_wol[(size_t)DD*DD];
__device__ __nv_bfloat16 g_w1h[(size_t)DD*FF], g_w1l[(size_t)DD*FF];
__device__ __nv_bfloat16 g_w2h[(size_t)FF*DD], g_w2l[(size_t)FF*DD];

// ---------------- helpers ----------------
__device__ __forceinline__ uint32_t smem_u32(const void* p) {
    uint32_t a;
    asm("{ .reg .u64 t; cvta.to.shared.u64 t, %1; cvt.u32.u64 %0, t; }" : "=r"(a) : "l"(p));
    return a;
}
__device__ __forceinline__ void ldm_x4(uint32_t& r0, uint32_t& r1, uint32_t& r2, uint32_t& r3, uint32_t a) {
    asm volatile("ldmatrix.sync.aligned.m8n8.x4.shared.b16 {%0,%1,%2,%3}, [%4];"
                 : "=r"(r0), "=r"(r1), "=r"(r2), "=r"(r3) : "r"(a));
}
__device__ __forceinline__ void ldm_x4_t(uint32_t& r0, uint32_t& r1, uint32_t& r2, uint32_t& r3, uint32_t a) {
    asm volatile("ldmatrix.sync.aligned.m8n8.x4.trans.shared.b16 {%0,%1,%2,%3}, [%4];"
                 : "=r"(r0), "=r"(r1), "=r"(r2), "=r"(r3) : "r"(a));
}
__device__ __forceinline__ void ldm_x2(uint32_t& r0, uint32_t& r1, uint32_t a) {
    asm volatile("ldmatrix.sync.aligned.m8n8.x2.shared.b16 {%0,%1}, [%2];"
                 : "=r"(r0), "=r"(r1) : "r"(a));
}
__device__ __forceinline__ void mma16816(float* c, const uint32_t* a, const uint32_t* b) {
    asm volatile("mma.sync.aligned.m16n8k16.row.col.f32.bf16.bf16.f32 "
                 "{%0,%1,%2,%3}, {%4,%5,%6,%7}, {%8,%9}, {%0,%1,%2,%3};"
                 : "+f"(c[0]), "+f"(c[1]), "+f"(c[2]), "+f"(c[3])
                 : "r"(a[0]), "r"(a[1]), "r"(a[2]), "r"(a[3]), "r"(b[0]), "r"(b[1]));
}
__device__ __forceinline__ uint32_t pack2(float a, float b) {
    __nv_bfloat162 t = __floats2bfloat162_rn(a, b);
    return *(uint32_t*)&t;
}
#define CP_ASYNC16(dst, src) asm volatile("cp.async.cg.shared.global [%0], [%1], 16;" :: "r"(dst), "l"(src))
#define CP_COMMIT()  asm volatile("cp.async.commit_group;")
#define CP_WAIT0()   asm volatile("cp.async.wait_group 0;")
#define CP_WAIT1()   asm volatile("cp.async.wait_group 1;")

// ---------------- LayerNorm -> split bf16 hi/lo ----------------
__global__ void ln_kernel(const float* __restrict__ x,
                          const float* __restrict__ g,
                          const float* __restrict__ b,
                          __nv_bfloat16* __restrict__ oh,
                          __nv_bfloat16* __restrict__ ol)
{
    const int row = blockIdx.x;
    const float* xr = x + (size_t)row * DD;

    float s = 0.f, s2 = 0.f;
    for (int i = threadIdx.x; i < DD; i += blockDim.x) {
        float v = xr[i];
        s += v; s2 += v * v;
    }
    __shared__ float red[64];
    for (int o = 16; o; o >>= 1) {
        s  += __shfl_xor_sync(0xffffffffu, s,  o);
        s2 += __shfl_xor_sync(0xffffffffu, s2, o);
    }
    int wid = threadIdx.x >> 5, lid = threadIdx.x & 31;
    if (lid == 0) { red[wid] = s; red[wid + 32] = s2; }
    __syncthreads();
    if (wid == 0) {
        int nw = blockDim.x >> 5;
        s  = (lid < nw) ? red[lid] : 0.f;
        s2 = (lid < nw) ? red[lid + 32] : 0.f;
        for (int o = 16; o; o >>= 1) {
            s  += __shfl_xor_sync(0xffffffffu, s,  o);
            s2 += __shfl_xor_sync(0xffffffffu, s2, o);
        }
        if (lid == 0) { red[0] = s; red[1] = s2; }
    }
    __syncthreads();
    float mean = red[0] * (1.0f / DD);
    float var  = red[1] * (1.0f / DD) - mean * mean;
    float inv  = rsqrtf(var + 1e-5f);
    for (int i = threadIdx.x; i < DD; i += blockDim.x) {
        float v = (xr[i] - mean) * inv * g[i] + b[i];
        __nv_bfloat16 h = __float2bfloat16(v);
        oh[(size_t)row * DD + i] = h;
        ol[(size_t)row * DD + i] = __float2bfloat16(v - __bfloat162float(h));
    }
}

// ---------------- weight transpose + split: w[K,N] -> th/tl[N,K] ----------
__global__ void wprep_kernel(const float* __restrict__ w,
                             __nv_bfloat16* __restrict__ th,
                             __nv_bfloat16* __restrict__ tl, int K, int N)
{
    __shared__ float t[32][33];
    int nx0 = blockIdx.x * 32, ky0 = blockIdx.y * 32;
    int tx = threadIdx.x, ty = threadIdx.y;   // 32 x 8
    #pragma unroll
    for (int d = 0; d < 4; d++)
        t[ty + d * 8][tx] = w[(size_t)(ky0 + ty + d * 8) * N + nx0 + tx];
    __syncthreads();
    #pragma unroll
    for (int d = 0; d < 4; d++) {
        float v = t[tx][ty + d * 8];
        __nv_bfloat16 h = __float2bfloat16(v);
        size_t o = (size_t)(nx0 + ty + d * 8) * K + ky0 + tx;
        th[o] = h;
        tl[o] = __float2bfloat16(v - __bfloat162float(h));
    }
}

// ---------------- mma.sync split-bf16 GEMM, 512 threads -------------------
// C[M,N] = (Ah+Al)[M,K] @ (Bh+Bl)[N,K]^T, fp32 accum.
// CTA tile 128x128, BK=32, 512 threads (16 warps 4m x 4n, warp tile 32x32),
// 2-stage cp.async. Packed x4 ldmatrix for B (2 n-tiles + both k-halves).
#define LDT 40                    // smem row stride (32 + 8 pad) -> 80B
#define GARR (128*LDT*2)          // 10240 B per array
#define GSTG (4*GARR)             // 40960 B per stage
#define SMEM_GEMM (2*GSTG)        // 81920 B

__global__ void __launch_bounds__(512, 1)
mma_gemm(const __nv_bfloat16* __restrict__ Ah, const __nv_bfloat16* __restrict__ Al,
         const __nv_bfloat16* __restrict__ Bh, const __nv_bfloat16* __restrict__ Bl,
         const float* __restrict__ bias, const float* __restrict__ resid,
         float* __restrict__ Cf, __nv_bfloat16* __restrict__ Ch,
         __nv_bfloat16* __restrict__ Cl, int M, int N, int K, int dogelu)
{
    extern __shared__ char gsm[];
    const uint32_t sb = smem_u32(gsm);

    const int tid = threadIdx.x, lane = tid & 31, wid = tid >> 5;
    const int wm = wid & 3, wn = wid >> 2;           // 4m x 4n warps, tile 32x32
    const int bm = blockIdx.y * 128, bn = blockIdx.x * 128;

    float acc[2][4][4];
    #pragma unroll
    for (int i = 0; i < 2; i++)
        #pragma unroll
        for (int j = 0; j < 4; j++)
            #pragma unroll
            for (int r = 0; r < 4; r++) acc[i][j][r] = 0.f;

    // per-thread load coords: 1 uint4 per array (512 threads cover 128x32)
    const int l_r = tid >> 2, l_c8 = (tid & 3) * 8;
    // A x4 (16x16): row = lane&15, k-half = lane>>4
    const uint32_t a_off = (uint32_t)((lane & 15) * LDT + (lane >> 4) * 8) * 2;
    // B packed x4: lanes 0-7:(n0,k0) 8-15:(n0,k1) 16-23:(n0+8,k0) 24-31:(n0+8,k1)
    const uint32_t bp_off = (uint32_t)(((lane & 7) + ((lane >> 4) & 1) * 8) * LDT
                                       + ((lane >> 3) & 1) * 8) * 2;

    const int T = K >> 5;

    // prologue: stages 0, 1
    #pragma unroll
    for (int p = 0; p < 2; p++) {
        const int kn = p << 5;
        const uint32_t st = (uint32_t)p * GSTG;
        uint32_t so = st + (uint32_t)(l_r * LDT + l_c8) * 2;
        size_t ga = (size_t)(bm + l_r) * K + kn + l_c8;
        size_t gb = (size_t)(bn + l_r) * K + kn + l_c8;
        CP_ASYNC16(sb + 0*GARR + so, Ah + ga);
        CP_ASYNC16(sb + 1*GARR + so, Al + ga);
        CP_ASYNC16(sb + 2*GARR + so, Bh + gb);
        CP_ASYNC16(sb + 3*GARR + so, Bl + gb);
        CP_COMMIT();
    }

    for (int t = 0; t < T; t++) {
        if (t + 1 < T) { CP_WAIT1(); } else { CP_WAIT0(); }
        __syncthreads();

        const uint32_t st = (uint32_t)(t & 1) * GSTG;
        const uint32_t sAh_b = sb + st, sAl_b = sb + st + GARR;
        const uint32_t sBh_b = sb + st + 2*GARR, sBl_b = sb + st + 3*GARR;

        #pragma unroll
        for (int ks = 0; ks < 2; ks++) {
            const uint32_t kso = ks * 16 * 2;
            uint32_t ah[2][4], al[2][4], bh[4][2], bl[4][2];
            #pragma unroll
            for (int mt = 0; mt < 2; mt++) {
                uint32_t base = (uint32_t)((wm * 32 + mt * 16) * LDT) * 2 + kso + a_off;
                ldm_x4(ah[mt][0], ah[mt][1], ah[mt][2], ah[mt][3], sAh_b + base);
                ldm_x4(al[mt][0], al[mt][1], al[mt][2], al[mt][3], sAl_b + base);
            }
            #pragma unroll
            for (int p = 0; p < 2; p++) {    // nt pair (2p, 2p+1)
                uint32_t base = (uint32_t)((wn * 32 + p * 16) * LDT) * 2 + kso + bp_off;
                ldm_x4(bh[2*p][0], bh[2*p][1], bh[2*p+1][0], bh[2*p+1][1], sBh_b + base);
                ldm_x4(bl[2*p][0], bl[2*p][1], bl[2*p+1][0], bl[2*p+1][1], sBl_b + base);
            }
            #pragma unroll
            for (int mt = 0; mt < 2; mt++)
                #pragma unroll
                for (int nt = 0; nt < 4; nt++) {
                    mma16816(acc[mt][nt], ah[mt], bh[nt]);
                    mma16816(acc[mt][nt], ah[mt], bl[nt]);
                    mma16816(acc[mt][nt], al[mt], bh[nt]);
                }
        }
        __syncthreads();

        if (t + 2 < T) {
            const int kn = (t + 2) << 5;
            const uint32_t sti = (uint32_t)(t & 1) * GSTG;  // (t+2)&1 == t&1
            uint32_t so = sti + (uint32_t)(l_r * LDT + l_c8) * 2;
            size_t ga = (size_t)(bm + l_r) * K + kn + l_c8;
            size_t gb = (size_t)(bn + l_r) * K + kn + l_c8;
            CP_ASYNC16(sb + 0*GARR + so, Ah + ga);
            CP_ASYNC16(sb + 1*GARR + so, Al + ga);
            CP_ASYNC16(sb + 2*GARR + so, Bh + gb);
            CP_ASYNC16(sb + 3*GARR + so, Bl + gb);
            CP_COMMIT();
        }
    }

    // epilogue
    const int mrow = bm + wm * 32 + (lane >> 2);
    const int ncol = bn + wn * 32 + (lane & 3) * 2;
    #pragma unroll
    for (int mt = 0; mt < 2; mt++) {
        #pragma unroll
        for (int half = 0; half < 2; half++) {
            int row = mrow + mt * 16 + half * 8;
            #pragma unroll
            for (int nt = 0; nt < 4; nt++) {
                int col = ncol + nt * 8;
                float v0 = acc[mt][nt][half * 2 + 0];
                float v1 = acc[mt][nt][half * 2 + 1];
                if (bias) { v0 += __ldg(bias + col); v1 += __ldg(bias + col + 1); }
                if (dogelu) {
                    v0 = 0.5f * v0 * (1.0f + erff(v0 * 0.70710678118654752f));
                    v1 = 0.5f * v1 * (1.0f + erff(v1 * 0.70710678118654752f));
                }
                size_t o = (size_t)row * N + col;
                if (resid) { v0 += resid[o]; v1 += resid[o + 1]; }
                if (Cf) { *(float2*)(Cf + o) = make_float2(v0, v1); }
                if (Ch) {
                    __nv_bfloat16 h0 = __float2bfloat16(v0);
                    __nv_bfloat16 h1 = __float2bfloat16(v1);
                    __nv_bfloat162 hp; hp.x = h0; hp.y = h1;
                    __nv_bfloat162 lp;
                    lp.x = __float2bfloat16(v0 - __bfloat162float(h0));
                    lp.y = __float2bfloat16(v1 - __bfloat162float(h1));
                    *(__nv_bfloat162*)(Ch + o) = hp;
                    *(__nv_bfloat162*)(Cl + o) = lp;
                }
            }
        }
    }
}

// ---------------- Flash attention, mma.sync split-bf16, pipelined --------
// CTA: 256 threads (8 warps), 128 q-rows x one head, 64-key tiles,
// 2-stage cp.async pipeline for K/V/mask. Reads fused qkv buffers.
#define LDF 72
#define FQH 0
#define FQL 18432
#define FKV 36864                 // 4 arrays x 9216 per stage, 2 stages
#define KVSTG 36864
#define FMK (FKV + 2*KVSTG)       // 110592; 2 x 32768
#define MKSTG 32768
#define SMEM_FLASH (FMK + 2*MKSTG)   // 176128

__global__ void __launch_bounds__(256, 1)
flash_mma(const __nv_bfloat16* __restrict__ qkvh, const __nv_bfloat16* __restrict__ qkvl,
          const int* __restrict__ mask,
          __nv_bfloat16* __restrict__ Oh, __nv_bfloat16* __restrict__ Ol)
{
    extern __shared__ char fsm[];
    const uint32_t sb = smem_u32(fsm);

    const int b = blockIdx.z, h = blockIdx.y;
    const int q0 = blockIdx.x * 128;
    const int tid = threadIdx.x, lane = tid & 31, w = tid >> 5;

    // ---- prologue: Q tile (group 0), KV+mask tile 0 (group 1) ----
    #pragma unroll
    for (int j = 0; j < 4; j++) {
        int e = tid + j * 256;           // 1024 chunks
        int r = e >> 3, c8 = (e & 7) * 8;
        size_t gq = (size_t)(b * SS + q0 + r) * QKD + h * HD + c8;
        uint32_t so = (uint32_t)(r * LDF + c8) * 2;
        CP_ASYNC16(sb + FQH + so, qkvh + gq);
        CP_ASYNC16(sb + FQL + so, qkvl + gq);
    }
    CP_COMMIT();
    {
        const uint32_t kvb = sb + FKV, mkb = sb + FMK;
        #pragma unroll
        for (int j = 0; j < 2; j++) {
            int e = tid + j * 256;       // 512 chunks
            int r = e >> 3, c8 = (e & 7) * 8;
            size_t gk = (size_t)(b * SS + r) * QKD + DD + h * HD + c8;
            uint32_t so = (uint32_t)(r * LDF + c8) * 2;
            CP_ASYNC16(kvb + 0*9216  + so, qkvh + gk);
            CP_ASYNC16(kvb + 1*9216  + so, qkvl + gk);
            CP_ASYNC16(kvb + 2*9216  + so, qkvh + gk + DD);
            CP_ASYNC16(kvb + 3*9216  + so, qkvl + gk + DD);
        }
        #pragma unroll
        for (int j = 0; j < 8; j++) {
            int e = tid + j * 256;       // 2048 int4
            int r = e >> 4, c4 = (e & 15) * 4;
            CP_ASYNC16(mkb + (uint32_t)(r * 64 + c4) * 4,
                       mask + (size_t)(b * SS + q0 + r) * SS + c4);
        }
        CP_COMMIT();
    }

    CP_WAIT1();           // Q ready (tile0 may still be in flight)
    __syncthreads();

    const uint32_t a_off = (uint32_t)((lane & 15) * LDF + (lane >> 4) * 8) * 2;
    const uint32_t b_off = (uint32_t)((lane & 7) * LDF + ((lane >> 3) & 1) * 8) * 2;

    uint32_t qhf[4][4], qlf[4][4];
    #pragma unroll
    for (int ks = 0; ks < 4; ks++) {
        uint32_t base = (uint32_t)(w * 16 * LDF) * 2 + (uint32_t)(ks * 16) * 2 + a_off;
        ldm_x4(qhf[ks][0], qhf[ks][1], qhf[ks][2], qhf[ks][3], sb + FQH + base);
        ldm_x4(qlf[ks][0], qlf[ks][1], qlf[ks][2], qlf[ks][3], sb + FQL + base);
    }

    float oacc[8][4];
    #pragma unroll
    for (int i = 0; i < 8; i++)
        #pragma unroll
        for (int j = 0; j < 4; j++) oacc[i][j] = 0.f;
    float m0 = -INFINITY, m1 = -INFINITY, l0 = 0.f, l1 = 0.f;
    int any0 = 0, any1 = 0;
    const int lr0 = lane >> 2;

    const int T = SS / 64;
    for (int t = 0; t < T; t++) {
        // prefetch tile t+1 into stage (t+1)&1
        if (t + 1 < T) {
            const int t0n = (t + 1) * 64;
            const uint32_t kvb = sb + FKV + (uint32_t)((t + 1) & 1) * KVSTG;
            const uint32_t mkb = sb + FMK + (uint32_t)((t + 1) & 1) * MKSTG;
            #pragma unroll
            for (int j = 0; j < 2; j++) {
                int e = tid + j * 256;
                int r = e >> 3, c8 = (e & 7) * 8;
                size_t gk = (size_t)(b * SS + t0n + r) * QKD + DD + h * HD + c8;
                uint32_t so = (uint32_t)(r * LDF + c8) * 2;
                CP_ASYNC16(kvb + 0*9216 + so, qkvh + gk);
                CP_ASYNC16(kvb + 1*9216 + so, qkvl + gk);
                CP_ASYNC16(kvb + 2*9216 + so, qkvh + gk + DD);
                CP_ASYNC16(kvb + 3*9216 + so, qkvl + gk + DD);
            }
            #pragma unroll
            for (int j = 0; j < 8; j++) {
                int e = tid + j * 256;
                int r = e >> 4, c4 = (e & 15) * 4;
                CP_ASYNC16(mkb + (uint32_t)(r * 64 + c4) * 4,
                           mask + (size_t)(b * SS + q0 + r) * SS + t0n + c4);
            }
            CP_COMMIT();
            CP_WAIT1();
        } else {
            CP_WAIT0();
        }
        __syncthreads();

        const uint32_t kvb = sb + FKV + (uint32_t)(t & 1) * KVSTG;
        const uint32_t skh_b = kvb, skl_b = kvb + 9216;
        const uint32_t svh_b = kvb + 18432, svl_b = kvb + 27648;
        const int* smsk = (const int*)(fsm + FMK + (size_t)(t & 1) * MKSTG);

        // scores S[16 q][64 k] per warp
        float sc[8][4];
        #pragma unroll
        for (int i = 0; i < 8; i++)
            #pragma unroll
            for (int j = 0; j < 4; j++) sc[i][j] = 0.f;

        #pragma unroll
        for (int ks = 0; ks < 4; ks++) {
            uint32_t khf[8][2], klf[8][2];
            #pragma unroll
            for (int nt = 0; nt < 8; nt++) {
                uint32_t base = (uint32_t)(nt * 8 * LDF) * 2 + (uint32_t)(ks * 16) * 2 + b_off;
                ldm_x2(khf[nt][0], khf[nt][1], skh_b + base);
                ldm_x2(klf[nt][0], klf[nt][1], skl_b + base);
            }
            #pragma unroll
            for (int nt = 0; nt < 8; nt++) {
                mma16816(sc[nt], qhf[ks], khf[nt]);
                mma16816(sc[nt], qhf[ks], klf[nt]);
                mma16816(sc[nt], qlf[ks], khf[nt]);
            }
        }

        // mask + scale + row max
        float tmax0 = -INFINITY, tmax1 = -INFINITY;
        #pragma unroll
        for (int nt = 0; nt < 8; nt++) {
            int c = nt * 8 + (lane & 3) * 2;
            int2 mv0 = *(const int2*)&smsk[(w * 16 + lr0) * 64 + c];
            int2 mv1 = *(const int2*)&smsk[(w * 16 + lr0 + 8) * 64 + c];
            any0 |= mv0.x | mv0.y;
            any1 |= mv1.x | mv1.y;
            sc[nt][0] = mv0.x ? sc[nt][0] * 0.125f : -1e30f;
            sc[nt][1] = mv0.y ? sc[nt][1] * 0.125f : -1e30f;
            sc[nt][2] = mv1.x ? sc[nt][2] * 0.125f : -1e30f;
            sc[nt][3] = mv1.y ? sc[nt][3] * 0.125f : -1e30f;
            tmax0 = fmaxf(tmax0, fmaxf(sc[nt][0], sc[nt][1]));
            tmax1 = fmaxf(tmax1, fmaxf(sc[nt][2], sc[nt][3]));
        }
        tmax0 = fmaxf(tmax0, __shfl_xor_sync(0xffffffffu, tmax0, 1));
        tmax0 = fmaxf(tmax0, __shfl_xor_sync(0xffffffffu, tmax0, 2));
        tmax1 = fmaxf(tmax1, __shfl_xor_sync(0xffffffffu, tmax1, 1));
        tmax1 = fmaxf(tmax1, __shfl_xor_sync(0xffffffffu, tmax1, 2));

        float mn0 = fmaxf(m0, tmax0), mn1 = fmaxf(m1, tmax1);
        float corr0 = __expf(m0 - mn0), corr1 = __expf(m1 - mn1);
        m0 = mn0; m1 = mn1;

        float ps0 = 0.f, ps1 = 0.f;
        #pragma unroll
        for (int nt = 0; nt < 8; nt++) {
            sc[nt][0] = __expf(sc[nt][0] - mn0);
            sc[nt][1] = __expf(sc[nt][1] - mn0);
            sc[nt][2] = __expf(sc[nt][2] - mn1);
            sc[nt][3] = __expf(sc[nt][3] - mn1);
            ps0 += sc[nt][0] + sc[nt][1];
            ps1 += sc[nt][2] + sc[nt][3];
        }
        ps0 += __shfl_xor_sync(0xffffffffu, ps0, 1);
        ps0 += __shfl_xor_sync(0xffffffffu, ps0, 2);
        ps1 += __shfl_xor_sync(0xffffffffu, ps1, 1);
        ps1 += __shfl_xor_sync(0xffffffffu, ps1, 2);
        l0 = l0 * corr0 + ps0;
        l1 = l1 * corr1 + ps1;

        #pragma unroll
        for (int d = 0; d < 8; d++) {
            oacc[d][0] *= corr0; oacc[d][1] *= corr0;
            oacc[d][2] *= corr1; oacc[d][3] *= corr1;
        }

        // PV
        #pragma unroll
        for (int kc = 0; kc < 4; kc++) {
            uint32_t pha[4], pla[4];
            {
                float p00 = sc[2*kc][0],   p01 = sc[2*kc][1];
                float p02 = sc[2*kc][2],   p03 = sc[2*kc][3];
                float p10 = sc[2*kc+1][0], p11 = sc[2*kc+1][1];
                float p12 = sc[2*kc+1][2], p13 = sc[2*kc+1][3];
                __nv_bfloat16 hh;
                float r00, r01, r02, r03, r10, r11, r12, r13;
                hh = __float2bfloat16(p00); r00 = p00 - __bfloat162float(hh);
                hh = __float2bfloat16(p01); r01 = p01 - __bfloat162float(hh);
                hh = __float2bfloat16(p02); r02 = p02 - __bfloat162float(hh);
                hh = __float2bfloat16(p03); r03 = p03 - __bfloat162float(hh);
                hh = __float2bfloat16(p10); r10 = p10 - __bfloat162float(hh);
                hh = __float2bfloat16(p11); r11 = p11 - __bfloat162float(hh);
                hh = __float2bfloat16(p12); r12 = p12 - __bfloat162float(hh);
                hh = __float2bfloat16(p13); r13 = p13 - __bfloat162float(hh);
                pha[0] = pack2(p00, p01); pha[1] = pack2(p02, p03);
                pha[2] = pack2(p10, p11); pha[3] = pack2(p12, p13);
                pla[0] = pack2(r00, r01); pla[1] = pack2(r02, r03);
                pla[2] = pack2(r10, r11); pla[3] = pack2(r12, r13);
            }
            #pragma unroll
            for (int nt2 = 0; nt2 < 4; nt2++) {
                int key = kc * 16 + ((lane >> 3) & 1) * 8 + (lane & 7);
                int dimb = nt2 * 16 + (lane >> 4) * 8;
                uint32_t ad = (uint32_t)(key * LDF + dimb) * 2;
                uint32_t vh0, vh1, vh2, vh3, vl0, vl1, vl2, vl3;
                ldm_x4_t(vh0, vh1, vh2, vh3, svh_b + ad);
                ldm_x4_t(vl0, vl1, vl2, vl3, svl_b + ad);
                uint32_t bh0[2] = {vh0, vh1}, bh1[2] = {vh2, vh3};
                uint32_t bl0[2] = {vl0, vl1}, bl1[2] = {vl2, vl3};
                mma16816(oacc[nt2*2],     pha, bh0);
                mma16816(oacc[nt2*2],     pha, bl0);
                mma16816(oacc[nt2*2],     pla, bh0);
                mma16816(oacc[nt2*2 + 1], pha, bh1);
                mma16816(oacc[nt2*2 + 1], pha, bl1);
                mma16816(oacc[nt2*2 + 1], pla, bh1);
            }
        }
        __syncthreads();
    }

    // finalize
    any0 |= __shfl_xor_sync(0xffffffffu, any0, 1);
    any0 |= __shfl_xor_sync(0xffffffffu, any0, 2);
    any1 |= __shfl_xor_sync(0xffffffffu, any1, 1);
    any1 |= __shfl_xor_sync(0xffffffffu, any1, 2);
    float inv0 = (any0 && l0 > 0.f) ? (1.0f / l0) : 0.0f;
    float inv1 = (any1 && l1 > 0.f) ? (1.0f / l1) : 0.0f;

    const int row0 = b * SS + q0 + w * 16 + lr0;
    #pragma unroll
    for (int nt = 0; nt < 8; nt++) {
        int col = h * HD + nt * 8 + (lane & 3) * 2;
        {
            float v0 = oacc[nt][0] * inv0, v1 = oacc[nt][1] * inv0;
            __nv_bfloat16 h0 = __float2bfloat16(v0), h1 = __float2bfloat16(v1);
            __nv_bfloat162 hp; hp.x = h0; hp.y = h1;
            __nv_bfloat162 lp;
            lp.x = __float2bfloat16(v0 - __bfloat162float(h0));
            lp.y = __float2bfloat16(v1 - __bfloat162float(h1));
            size_t o = (size_t)row0 * DD + col;
            *(__nv_bfloat162*)(Oh + o) = hp;
            *(__nv_bfloat162*)(Ol + o) = lp;
        }
        {
            float v0 = oacc[nt][2] * inv1, v1 = oacc[nt][3] * inv1;
            __nv_bfloat16 h0 = __float2bfloat16(v0), h1 = __float2bfloat16(v1);
            __nv_bfloat162 hp; hp.x = h0; hp.y = h1;
            __nv_bfloat162 lp;
            lp.x = __float2bfloat16(v0 - __bfloat162float(h0));
            lp.y = __float2bfloat16(v1 - __bfloat162float(h1));
            size_t o = (size_t)(row0 + 8) * DD + col;
            *(__nv_bfloat162*)(Oh + o) = hp;
            *(__nv_bfloat162*)(Ol + o) = lp;
        }
    }
}

// ---------------- launch ----------------
extern "C" void kernel_launch(void* const* d_in, const int* in_sizes, int n_in,
                              void* d_out, int out_size)
{
    const float* x      = (const float*)d_in[0];
    const int*   mask   = (const int*)d_in[1];
    const float* ln1_g  = (const float*)d_in[2];
    const float* ln1_b  = (const float*)d_in[3];
    const float* wq     = (const float*)d_in[4];
    const float* wk     = (const float*)d_in[5];
    const float* wv     = (const float*)d_in[6];
    const float* wo     = (const float*)d_in[7];
    const float* bo     = (const float*)d_in[8];
    const float* ln2_g  = (const float*)d_in[9];
    const float* ln2_b  = (const float*)d_in[10];
    const float* w1     = (const float*)d_in[11];
    const float* b1     = (const float*)d_in[12];
    const float* w2     = (const float*)d_in[13];
    const float* b2     = (const float*)d_in[14];
    float* out = (float*)d_out;

    __nv_bfloat16 *lnh, *lnl, *qkvh, *qkvl, *atth, *attl, *hh, *hl;
    __nv_bfloat16 *wqkvh, *wqkvl, *woh, *wol, *w1h, *w1l, *w2h, *w2l;
    float *x1;
    cudaGetSymbolAddress((void**)&lnh,   g_lnh);   cudaGetSymbolAddress((void**)&lnl,   g_lnl);
    cudaGetSymbolAddress((void**)&qkvh,  g_qkvh);  cudaGetSymbolAddress((void**)&qkvl,  g_qkvl);
    cudaGetSymbolAddress((void**)&atth,  g_atth);  cudaGetSymbolAddress((void**)&attl,  g_attl);
    cudaGetSymbolAddress((void**)&x1,    g_x1);
    cudaGetSymbolAddress((void**)&hh,    g_hh);    cudaGetSymbolAddress((void**)&hl,    g_hl);
    cudaGetSymbolAddress((void**)&wqkvh, g_wqkvh); cudaGetSymbolAddress((void**)&wqkvl, g_wqkvl);
    cudaGetSymbolAddress((void**)&woh,   g_woh);   cudaGetSymbolAddress((void**)&wol,   g_wol);
    cudaGetSymbolAddress((void**)&w1h,   g_w1h);   cudaGetSymbolAddress((void**)&w1l,   g_w1l);
    cudaGetSymbolAddress((void**)&w2h,   g_w2h);   cudaGetSymbolAddress((void**)&w2l,   g_w2l);

    cudaFuncSetAttribute(mma_gemm,  cudaFuncAttributeMaxDynamicSharedMemorySize, SMEM_GEMM);
    cudaFuncSetAttribute(flash_mma, cudaFuncAttributeMaxDynamicSharedMemorySize, SMEM_FLASH);

    // 0) weight transpose + split; q/k/v concatenated along N in wqkv
    dim3 tb(32, 8);
    wprep_kernel<<<dim3(DD/32, DD/32), tb>>>(wq, wqkvh,                     wqkvl,                     DD, DD);
    wprep_kernel<<<dim3(DD/32, DD/32), tb>>>(wk, wqkvh + (size_t)DD*DD,     wqkvl + (size_t)DD*DD,     DD, DD);
    wprep_kernel<<<dim3(DD/32, DD/32), tb>>>(wv, wqkvh + (size_t)2*DD*DD,   wqkvl + (size_t)2*DD*DD,   DD, DD);
    wprep_kernel<<<dim3(DD/32, DD/32), tb>>>(wo, woh, wol, DD, DD);
    wprep_kernel<<<dim3(FF/32, DD/32), tb>>>(w1, w1h, w1l, DD, FF);
    wprep_kernel<<<dim3(DD/32, FF/32), tb>>>(w2, w2h, w2l, FF, DD);

    // 1) LN1 -> split
    ln_kernel<<<ROWS, 256>>>(x, ln1_g, ln1_b, lnh, lnl);

    // 2) fused QKV projection -> qkv split buffers [ROWS][3072]
    dim3 gQKV(QKD/128, ROWS/128);
    mma_gemm<<<gQKV, 512, SMEM_GEMM>>>(lnh, lnl, wqkvh, wqkvl, nullptr, nullptr,
                                       nullptr, qkvh, qkvl, ROWS, QKD, DD, 0);

    // 3) attention (tensor cores, pipelined) -> split output
    dim3 gF(SS/128, HH, BB);
    flash_mma<<<gF, 256, SMEM_FLASH>>>(qkvh, qkvl, mask, atth, attl);

    // 4) output projection + bias + residual -> x1 (fp32)
    dim3 gO(DD/128, ROWS/128);
    mma_gemm<<<gO, 512, SMEM_GEMM>>>(atth, attl, woh, wol, bo, x, x1, nullptr, nullptr, ROWS, DD, DD, 0);

    // 5) LN2 -> split
    ln_kernel<<<ROWS, 256>>>(x1, ln2_g, ln2_b, lnh, lnl);

    // 6) MLP up + bias + gelu -> split h
    dim3 gM1(FF/128, ROWS/128);
    mma_gemm<<<gM1, 512, SMEM_GEMM>>>(lnh, lnl, w1h, w1l, b1, nullptr, nullptr, hh, hl, ROWS, FF, DD, 1);

    // 7) MLP down + bias + residual -> out
    dim3 gM2(DD/128, ROWS/128);
    mma_gemm<<<gM2, 512, SMEM_GEMM>>>(hh, hl, w2h, w2l, b2, x1, out, nullptr, nullptr, ROWS, DD, FF, 0);
}

// round 11
// speedup vs baseline: 3.5592x; 1.2423x over previous
#include <cuda_runtime.h>
#include <cuda_fp16.h>
#include <math.h>
#include <stdint.h>

// Problem constants
#define BB 4
#define SS 2048
#define DD 1024
#define HH 16
#define HD 64
#define FF 4096
#define ROWS (BB*SS)          // 8192
#define QKD 3072              // fused qkv width

// ---------------- scratch (device globals; no allocation) ----------------
__device__ __half g_lnh[(size_t)ROWS * DD];
__device__ __half g_lnl[(size_t)ROWS * DD];
__device__ __half g_qkvh[(size_t)ROWS * QKD], g_qkvl[(size_t)ROWS * QKD];
__device__ __half g_atth[(size_t)ROWS * DD];
__device__ __half g_attl[(size_t)ROWS * DD];
__device__ float g_x1[(size_t)ROWS * DD];
__device__ __half g_hh[(size_t)ROWS * FF];
__device__ __half g_hl[(size_t)ROWS * FF];
// transposed weights (single fp16): wt[N][K]
__device__ __half g_wqkv[(size_t)QKD*DD];
__device__ __half g_wo[(size_t)DD*DD];
__device__ __half g_w1[(size_t)DD*FF];
__device__ __half g_w2[(size_t)FF*DD];

// ---------------- helpers ----------------
__device__ __forceinline__ uint32_t smem_u32(const void* p) {
    uint32_t a;
    asm("{ .reg .u64 t; cvta.to.shared.u64 t, %1; cvt.u32.u64 %0, t; }" : "=r"(a) : "l"(p));
    return a;
}
__device__ __forceinline__ void ldm_x4(uint32_t& r0, uint32_t& r1, uint32_t& r2, uint32_t& r3, uint32_t a) {
    asm volatile("ldmatrix.sync.aligned.m8n8.x4.shared.b16 {%0,%1,%2,%3}, [%4];"
                 : "=r"(r0), "=r"(r1), "=r"(r2), "=r"(r3) : "r"(a));
}
__device__ __forceinline__ void ldm_x4_t(uint32_t& r0, uint32_t& r1, uint32_t& r2, uint32_t& r3, uint32_t a) {
    asm volatile("ldmatrix.sync.aligned.m8n8.x4.trans.shared.b16 {%0,%1,%2,%3}, [%4];"
                 : "=r"(r0), "=r"(r1), "=r"(r2), "=r"(r3) : "r"(a));
}
__device__ __forceinline__ void ldm_x2(uint32_t& r0, uint32_t& r1, uint32_t a) {
    asm volatile("ldmatrix.sync.aligned.m8n8.x2.shared.b16 {%0,%1}, [%2];"
                 : "=r"(r0), "=r"(r1) : "r"(a));
}
__device__ __forceinline__ void mma16816(float* c, const uint32_t* a, const uint32_t* b) {
    asm volatile("mma.sync.aligned.m16n8k16.row.col.f32.f16.f16.f32 "
                 "{%0,%1,%2,%3}, {%4,%5,%6,%7}, {%8,%9}, {%0,%1,%2,%3};"
                 : "+f"(c[0]), "+f"(c[1]), "+f"(c[2]), "+f"(c[3])
                 : "r"(a[0]), "r"(a[1]), "r"(a[2]), "r"(a[3]), "r"(b[0]), "r"(b[1]));
}
__device__ __forceinline__ uint32_t pack2h(float a, float b) {
    __half2 t = __floats2half2_rn(a, b);
    return *(uint32_t*)&t;
}
#define CP_ASYNC16(dst, src) asm volatile("cp.async.cg.shared.global [%0], [%1], 16;" :: "r"(dst), "l"(src))
#define CP_COMMIT()  asm volatile("cp.async.commit_group;")
#define CP_WAIT0()   asm volatile("cp.async.wait_group 0;")
#define CP_WAIT1()   asm volatile("cp.async.wait_group 1;")

// ---------------- LayerNorm -> split fp16 hi/lo ----------------
__global__ void ln_kernel(const float* __restrict__ x,
                          const float* __restrict__ g,
                          const float* __restrict__ b,
                          __half* __restrict__ oh,
                          __half* __restrict__ ol)
{
    const int row = blockIdx.x;
    const float* xr = x + (size_t)row * DD;

    float s = 0.f, s2 = 0.f;
    for (int i = threadIdx.x; i < DD; i += blockDim.x) {
        float v = xr[i];
        s += v; s2 += v * v;
    }
    __shared__ float red[64];
    for (int o = 16; o; o >>= 1) {
        s  += __shfl_xor_sync(0xffffffffu, s,  o);
        s2 += __shfl_xor_sync(0xffffffffu, s2, o);
    }
    int wid = threadIdx.x >> 5, lid = threadIdx.x & 31;
    if (lid == 0) { red[wid] = s; red[wid + 32] = s2; }
    __syncthreads();
    if (wid == 0) {
        int nw = blockDim.x >> 5;
        s  = (lid < nw) ? red[lid] : 0.f;
        s2 = (lid < nw) ? red[lid + 32] : 0.f;
        for (int o = 16; o; o >>= 1) {
            s  += __shfl_xor_sync(0xffffffffu, s,  o);
            s2 += __shfl_xor_sync(0xffffffffu, s2, o);
        }
        if (lid == 0) { red[0] = s; red[1] = s2; }
    }
    __syncthreads();
    float mean = red[0] * (1.0f / DD);
    float var  = red[1] * (1.0f / DD) - mean * mean;
    float inv  = rsqrtf(var + 1e-5f);
    for (int i = threadIdx.x; i < DD; i += blockDim.x) {
        float v = (xr[i] - mean) * inv * g[i] + b[i];
        __half h = __float2half(v);
        oh[(size_t)row * DD + i] = h;
        ol[(size_t)row * DD + i] = __float2half(v - __half2float(h));
    }
}

// ---------------- weight transpose: w[K,N] -> th[N,K] fp16 ----------------
__global__ void wprep_kernel(const float* __restrict__ w,
                             __half* __restrict__ th, int K, int N)
{
    __shared__ float t[32][33];
    int nx0 = blockIdx.x * 32, ky0 = blockIdx.y * 32;
    int tx = threadIdx.x, ty = threadIdx.y;   // 32 x 8
    #pragma unroll
    for (int d = 0; d < 4; d++)
        t[ty + d * 8][tx] = w[(size_t)(ky0 + ty + d * 8) * N + nx0 + tx];
    __syncthreads();
    #pragma unroll
    for (int d = 0; d < 4; d++)
        th[(size_t)(nx0 + ty + d * 8) * K + ky0 + tx] = __float2half(t[tx][ty + d * 8]);
}

// ---------------- mma.sync fp16 2-term GEMM, 512 threads -------------------
// C[M,N] = (Ah+Al)[M,K] @ B[N,K]^T, fp32 accum. (B = fp16-rounded weights)
// CTA tile 128x128, BK=32, 512 threads (16 warps 4m x 4n, warp tile 32x32),
// 2-stage cp.async. Packed x4 ldmatrix for B.
#define LDT 40                    // smem row stride (32 + 8 pad) -> 80B
#define GARR (128*LDT*2)          // 10240 B per array
#define GSTG (3*GARR)             // 30720 B per stage (Ah, Al, B)
#define SMEM_GEMM (2*GSTG)        // 61440 B

__global__ void __launch_bounds__(512, 1)
mma_gemm(const __half* __restrict__ Ah, const __half* __restrict__ Al,
         const __half* __restrict__ B,
         const float* __restrict__ bias, const float* __restrict__ resid,
         float* __restrict__ Cf, __half* __restrict__ Ch,
         __half* __restrict__ Cl, int M, int N, int K, int dogelu)
{
    extern __shared__ char gsm[];
    const uint32_t sb = smem_u32(gsm);

    const int tid = threadIdx.x, lane = tid & 31, wid = tid >> 5;
    const int wm = wid & 3, wn = wid >> 2;           // 4m x 4n warps, tile 32x32
    const int bm = blockIdx.y * 128, bn = blockIdx.x * 128;

    float acc[2][4][4];
    #pragma unroll
    for (int i = 0; i < 2; i++)
        #pragma unroll
        for (int j = 0; j < 4; j++)
            #pragma unroll
            for (int r = 0; r < 4; r++) acc[i][j][r] = 0.f;

    const int l_r = tid >> 2, l_c8 = (tid & 3) * 8;
    const uint32_t a_off = (uint32_t)((lane & 15) * LDT + (lane >> 4) * 8) * 2;
    // B packed x4: lanes 0-7:(n0,k0) 8-15:(n0,k1) 16-23:(n0+8,k0) 24-31:(n0+8,k1)
    const uint32_t bp_off = (uint32_t)(((lane & 7) + ((lane >> 4) & 1) * 8) * LDT
                                       + ((lane >> 3) & 1) * 8) * 2;

    const int T = K >> 5;

    // prologue: stages 0, 1
    #pragma unroll
    for (int p = 0; p < 2; p++) {
        const int kn = p << 5;
        const uint32_t st = (uint32_t)p * GSTG;
        uint32_t so = st + (uint32_t)(l_r * LDT + l_c8) * 2;
        size_t ga = (size_t)(bm + l_r) * K + kn + l_c8;
        size_t gb = (size_t)(bn + l_r) * K + kn + l_c8;
        CP_ASYNC16(sb + 0*GARR + so, Ah + ga);
        CP_ASYNC16(sb + 1*GARR + so, Al + ga);
        CP_ASYNC16(sb + 2*GARR + so, B + gb);
        CP_COMMIT();
    }

    for (int t = 0; t < T; t++) {
        if (t + 1 < T) { CP_WAIT1(); } else { CP_WAIT0(); }
        __syncthreads();

        const uint32_t st = (uint32_t)(t & 1) * GSTG;
        const uint32_t sAh_b = sb + st, sAl_b = sb + st + GARR;
        const uint32_t sB_b  = sb + st + 2*GARR;

        #pragma unroll
        for (int ks = 0; ks < 2; ks++) {
            const uint32_t kso = ks * 16 * 2;
            uint32_t ah[2][4], al[2][4], bf[4][2];
            #pragma unroll
            for (int mt = 0; mt < 2; mt++) {
                uint32_t base = (uint32_t)((wm * 32 + mt * 16) * LDT) * 2 + kso + a_off;
                ldm_x4(ah[mt][0], ah[mt][1], ah[mt][2], ah[mt][3], sAh_b + base);
                ldm_x4(al[mt][0], al[mt][1], al[mt][2], al[mt][3], sAl_b + base);
            }
            #pragma unroll
            for (int p = 0; p < 2; p++) {    // nt pair (2p, 2p+1)
                uint32_t base = (uint32_t)((wn * 32 + p * 16) * LDT) * 2 + kso + bp_off;
                ldm_x4(bf[2*p][0], bf[2*p][1], bf[2*p+1][0], bf[2*p+1][1], sB_b + base);
            }
            #pragma unroll
            for (int mt = 0; mt < 2; mt++)
                #pragma unroll
                for (int nt = 0; nt < 4; nt++) {
                    mma16816(acc[mt][nt], ah[mt], bf[nt]);
                    mma16816(acc[mt][nt], al[mt], bf[nt]);
                }
        }
        __syncthreads();

        if (t + 2 < T) {
            const int kn = (t + 2) << 5;
            const uint32_t sti = (uint32_t)(t & 1) * GSTG;
            uint32_t so = sti + (uint32_t)(l_r * LDT + l_c8) * 2;
            size_t ga = (size_t)(bm + l_r) * K + kn + l_c8;
            size_t gb = (size_t)(bn + l_r) * K + kn + l_c8;
            CP_ASYNC16(sb + 0*GARR + so, Ah + ga);
            CP_ASYNC16(sb + 1*GARR + so, Al + ga);
            CP_ASYNC16(sb + 2*GARR + so, B + gb);
            CP_COMMIT();
        }
    }

    // epilogue
    const int mrow = bm + wm * 32 + (lane >> 2);
    const int ncol = bn + wn * 32 + (lane & 3) * 2;
    #pragma unroll
    for (int mt = 0; mt < 2; mt++) {
        #pragma unroll
        for (int half = 0; half < 2; half++) {
            int row = mrow + mt * 16 + half * 8;
            #pragma unroll
            for (int nt = 0; nt < 4; nt++) {
                int col = ncol + nt * 8;
                float v0 = acc[mt][nt][half * 2 + 0];
                float v1 = acc[mt][nt][half * 2 + 1];
                if (bias) { v0 += __ldg(bias + col); v1 += __ldg(bias + col + 1); }
                if (dogelu) {
                    v0 = 0.5f * v0 * (1.0f + erff(v0 * 0.70710678118654752f));
                    v1 = 0.5f * v1 * (1.0f + erff(v1 * 0.70710678118654752f));
                }
                size_t o = (size_t)row * N + col;
                if (resid) { v0 += resid[o]; v1 += resid[o + 1]; }
                if (Cf) { *(float2*)(Cf + o) = make_float2(v0, v1); }
                if (Ch) {
                    __half h0 = __float2half(v0);
                    __half h1 = __float2half(v1);
                    __half2 hp; hp.x = h0; hp.y = h1;
                    __half2 lp;
                    lp.x = __float2half(v0 - __half2float(h0));
                    lp.y = __float2half(v1 - __half2float(h1));
                    *(__half2*)(Ch + o) = hp;
                    *(__half2*)(Cl + o) = lp;
                }
            }
        }
    }
}

// ---------------- Flash attention, fp16 mma, pipelined --------------------
// CTA: 256 threads (8 warps), 128 q-rows x one head, 64-key tiles.
// QK 3-term (Qh.Kh + Qh.Kl + Ql.Kh); PV 2-term (Ph.Vh + Pl.Vh).
#define LDF 72
#define FQH 0
#define FQL 18432
#define FKV 36864                 // 3 arrays x 9216 per stage (Kh, Kl, Vh)
#define KVSTG 27648
#define FMK (FKV + 2*KVSTG)       // 92160; 2 x 32768
#define MKSTG 32768
#define SMEM_FLASH (FMK + 2*MKSTG)   // 157696

__global__ void __launch_bounds__(256, 1)
flash_mma(const __half* __restrict__ qkvh, const __half* __restrict__ qkvl,
          const int* __restrict__ mask,
          __half* __restrict__ Oh, __half* __restrict__ Ol)
{
    extern __shared__ char fsm[];
    const uint32_t sb = smem_u32(fsm);

    const int b = blockIdx.z, h = blockIdx.y;
    const int q0 = blockIdx.x * 128;
    const int tid = threadIdx.x, lane = tid & 31, w = tid >> 5;

    // ---- prologue: Q tile (group 0), KV+mask tile 0 (group 1) ----
    #pragma unroll
    for (int j = 0; j < 4; j++) {
        int e = tid + j * 256;           // 1024 chunks
        int r = e >> 3, c8 = (e & 7) * 8;
        size_t gq = (size_t)(b * SS + q0 + r) * QKD + h * HD + c8;
        uint32_t so = (uint32_t)(r * LDF + c8) * 2;
        CP_ASYNC16(sb + FQH + so, qkvh + gq);
        CP_ASYNC16(sb + FQL + so, qkvl + gq);
    }
    CP_COMMIT();
    {
        const uint32_t kvb = sb + FKV, mkb = sb + FMK;
        #pragma unroll
        for (int j = 0; j < 2; j++) {
            int e = tid + j * 256;       // 512 chunks
            int r = e >> 3, c8 = (e & 7) * 8;
            size_t gk = (size_t)(b * SS + r) * QKD + DD + h * HD + c8;
            uint32_t so = (uint32_t)(r * LDF + c8) * 2;
            CP_ASYNC16(kvb + 0*9216  + so, qkvh + gk);
            CP_ASYNC16(kvb + 1*9216  + so, qkvl + gk);
            CP_ASYNC16(kvb + 2*9216  + so, qkvh + gk + DD);
        }
        #pragma unroll
        for (int j = 0; j < 8; j++) {
            int e = tid + j * 256;       // 2048 int4
            int r = e >> 4, c4 = (e & 15) * 4;
            CP_ASYNC16(mkb + (uint32_t)(r * 64 + c4) * 4,
                       mask + (size_t)(b * SS + q0 + r) * SS + c4);
        }
        CP_COMMIT();
    }

    CP_WAIT1();           // Q ready (tile0 may still be in flight)
    __syncthreads();

    const uint32_t a_off = (uint32_t)((lane & 15) * LDF + (lane >> 4) * 8) * 2;
    const uint32_t b_off = (uint32_t)((lane & 7) * LDF + ((lane >> 3) & 1) * 8) * 2;

    uint32_t qhf[4][4], qlf[4][4];
    #pragma unroll
    for (int ks = 0; ks < 4; ks++) {
        uint32_t base = (uint32_t)(w * 16 * LDF) * 2 + (uint32_t)(ks * 16) * 2 + a_off;
        ldm_x4(qhf[ks][0], qhf[ks][1], qhf[ks][2], qhf[ks][3], sb + FQH + base);
        ldm_x4(qlf[ks][0], qlf[ks][1], qlf[ks][2], qlf[ks][3], sb + FQL + base);
    }

    float oacc[8][4];
    #pragma unroll
    for (int i = 0; i < 8; i++)
        #pragma unroll
        for (int j = 0; j < 4; j++) oacc[i][j] = 0.f;
    float m0 = -INFINITY, m1 = -INFINITY, l0 = 0.f, l1 = 0.f;
    int any0 = 0, any1 = 0;
    const int lr0 = lane >> 2;

    const int T = SS / 64;
    for (int t = 0; t < T; t++) {
        // prefetch tile t+1 into stage (t+1)&1
        if (t + 1 < T) {
            const int t0n = (t + 1) * 64;
            const uint32_t kvb = sb + FKV + (uint32_t)((t + 1) & 1) * KVSTG;
            const uint32_t mkb = sb + FMK + (uint32_t)((t + 1) & 1) * MKSTG;
            #pragma unroll
            for (int j = 0; j < 2; j++) {
                int e = tid + j * 256;
                int r = e >> 3, c8 = (e & 7) * 8;
                size_t gk = (size_t)(b * SS + t0n + r) * QKD + DD + h * HD + c8;
                uint32_t so = (uint32_t)(r * LDF + c8) * 2;
                CP_ASYNC16(kvb + 0*9216 + so, qkvh + gk);
                CP_ASYNC16(kvb + 1*9216 + so, qkvl + gk);
                CP_ASYNC16(kvb + 2*9216 + so, qkvh + gk + DD);
            }
            #pragma unroll
            for (int j = 0; j < 8; j++) {
                int e = tid + j * 256;
                int r = e >> 4, c4 = (e & 15) * 4;
                CP_ASYNC16(mkb + (uint32_t)(r * 64 + c4) * 4,
                           mask + (size_t)(b * SS + q0 + r) * SS + t0n + c4);
            }
            CP_COMMIT();
            CP_WAIT1();
        } else {
            CP_WAIT0();
        }
        __syncthreads();

        const uint32_t kvb = sb + FKV + (uint32_t)(t & 1) * KVSTG;
        const uint32_t skh_b = kvb, skl_b = kvb + 9216, svh_b = kvb + 18432;
        const int* smsk = (const int*)(fsm + FMK + (size_t)(t & 1) * MKSTG);

        // scores S[16 q][64 k] per warp (3-term)
        float sc[8][4];
        #pragma unroll
        for (int i = 0; i < 8; i++)
            #pragma unroll
            for (int j = 0; j < 4; j++) sc[i][j] = 0.f;

        #pragma unroll
        for (int ks = 0; ks < 4; ks++) {
            uint32_t khf[8][2], klf[8][2];
            #pragma unroll
            for (int nt = 0; nt < 8; nt++) {
                uint32_t base = (uint32_t)(nt * 8 * LDF) * 2 + (uint32_t)(ks * 16) * 2 + b_off;
                ldm_x2(khf[nt][0], khf[nt][1], skh_b + base);
                ldm_x2(klf[nt][0], klf[nt][1], skl_b + base);
            }
            #pragma unroll
            for (int nt = 0; nt < 8; nt++) {
                mma16816(sc[nt], qhf[ks], khf[nt]);
                mma16816(sc[nt], qhf[ks], klf[nt]);
                mma16816(sc[nt], qlf[ks], khf[nt]);
            }
        }

        // mask + scale + row max
        float tmax0 = -INFINITY, tmax1 = -INFINITY;
        #pragma unroll
        for (int nt = 0; nt < 8; nt++) {
            int c = nt * 8 + (lane & 3) * 2;
            int2 mv0 = *(const int2*)&smsk[(w * 16 + lr0) * 64 + c];
            int2 mv1 = *(const int2*)&smsk[(w * 16 + lr0 + 8) * 64 + c];
            any0 |= mv0.x | mv0.y;
            any1 |= mv1.x | mv1.y;
            sc[nt][0] = mv0.x ? sc[nt][0] * 0.125f : -1e30f;
            sc[nt][1] = mv0.y ? sc[nt][1] * 0.125f : -1e30f;
            sc[nt][2] = mv1.x ? sc[nt][2] * 0.125f : -1e30f;
            sc[nt][3] = mv1.y ? sc[nt][3] * 0.125f : -1e30f;
            tmax0 = fmaxf(tmax0, fmaxf(sc[nt][0], sc[nt][1]));
            tmax1 = fmaxf(tmax1, fmaxf(sc[nt][2], sc[nt][3]));
        }
        tmax0 = fmaxf(tmax0, __shfl_xor_sync(0xffffffffu, tmax0, 1));
        tmax0 = fmaxf(tmax0, __shfl_xor_sync(0xffffffffu, tmax0, 2));
        tmax1 = fmaxf(tmax1, __shfl_xor_sync(0xffffffffu, tmax1, 1));
        tmax1 = fmaxf(tmax1, __shfl_xor_sync(0xffffffffu, tmax1, 2));

        float mn0 = fmaxf(m0, tmax0), mn1 = fmaxf(m1, tmax1);
        float corr0 = __expf(m0 - mn0), corr1 = __expf(m1 - mn1);
        m0 = mn0; m1 = mn1;

        float ps0 = 0.f, ps1 = 0.f;
        #pragma unroll
        for (int nt = 0; nt < 8; nt++) {
            sc[nt][0] = __expf(sc[nt][0] - mn0);
            sc[nt][1] = __expf(sc[nt][1] - mn0);
            sc[nt][2] = __expf(sc[nt][2] - mn1);
            sc[nt][3] = __expf(sc[nt][3] - mn1);
            ps0 += sc[nt][0] + sc[nt][1];
            ps1 += sc[nt][2] + sc[nt][3];
        }
        ps0 += __shfl_xor_sync(0xffffffffu, ps0, 1);
        ps0 += __shfl_xor_sync(0xffffffffu, ps0, 2);
        ps1 += __shfl_xor_sync(0xffffffffu, ps1, 1);
        ps1 += __shfl_xor_sync(0xffffffffu, ps1, 2);
        l0 = l0 * corr0 + ps0;
        l1 = l1 * corr1 + ps1;

        #pragma unroll
        for (int d = 0; d < 8; d++) {
            oacc[d][0] *= corr0; oacc[d][1] *= corr0;
            oacc[d][2] *= corr1; oacc[d][3] *= corr1;
        }

        // PV (2-term: Ph.Vh + Pl.Vh)
        #pragma unroll
        for (int kc = 0; kc < 4; kc++) {
            uint32_t pha[4], pla[4];
            {
                float p00 = sc[2*kc][0],   p01 = sc[2*kc][1];
                float p02 = sc[2*kc][2],   p03 = sc[2*kc][3];
                float p10 = sc[2*kc+1][0], p11 = sc[2*kc+1][1];
                float p12 = sc[2*kc+1][2], p13 = sc[2*kc+1][3];
                __half hh;
                float r00, r01, r02, r03, r10, r11, r12, r13;
                hh = __float2half(p00); r00 = p00 - __half2float(hh);
                hh = __float2half(p01); r01 = p01 - __half2float(hh);
                hh = __float2half(p02); r02 = p02 - __half2float(hh);
                hh = __float2half(p03); r03 = p03 - __half2float(hh);
                hh = __float2half(p10); r10 = p10 - __half2float(hh);
                hh = __float2half(p11); r11 = p11 - __half2float(hh);
                hh = __float2half(p12); r12 = p12 - __half2float(hh);
                hh = __float2half(p13); r13 = p13 - __half2float(hh);
                pha[0] = pack2h(p00, p01); pha[1] = pack2h(p02, p03);
                pha[2] = pack2h(p10, p11); pha[3] = pack2h(p12, p13);
                pla[0] = pack2h(r00, r01); pla[1] = pack2h(r02, r03);
                pla[2] = pack2h(r10, r11); pla[3] = pack2h(r12, r13);
            }
            #pragma unroll
            for (int nt2 = 0; nt2 < 4; nt2++) {
                int key = kc * 16 + ((lane >> 3) & 1) * 8 + (lane & 7);
                int dimb = nt2 * 16 + (lane >> 4) * 8;
                uint32_t ad = (uint32_t)(key * LDF + dimb) * 2;
                uint32_t vh0, vh1, vh2, vh3;
                ldm_x4_t(vh0, vh1, vh2, vh3, svh_b + ad);
                uint32_t bh0[2] = {vh0, vh1}, bh1[2] = {vh2, vh3};
                mma16816(oacc[nt2*2],     pha, bh0);
                mma16816(oacc[nt2*2],     pla, bh0);
                mma16816(oacc[nt2*2 + 1], pha, bh1);
                mma16816(oacc[nt2*2 + 1], pla, bh1);
            }
        }
        __syncthreads();
    }

    // finalize
    any0 |= __shfl_xor_sync(0xffffffffu, any0, 1);
    any0 |= __shfl_xor_sync(0xffffffffu, any0, 2);
    any1 |= __shfl_xor_sync(0xffffffffu, any1, 1);
    any1 |= __shfl_xor_sync(0xffffffffu, any1, 2);
    float inv0 = (any0 && l0 > 0.f) ? (1.0f / l0) : 0.0f;
    float inv1 = (any1 && l1 > 0.f) ? (1.0f / l1) : 0.0f;

    const int row0 = b * SS + q0 + w * 16 + lr0;
    #pragma unroll
    for (int nt = 0; nt < 8; nt++) {
        int col = h * HD + nt * 8 + (lane & 3) * 2;
        {
            float v0 = oacc[nt][0] * inv0, v1 = oacc[nt][1] * inv0;
            __half h0 = __float2half(v0), h1 = __float2half(v1);
            __half2 hp; hp.x = h0; hp.y = h1;
            __half2 lp;
            lp.x = __float2half(v0 - __half2float(h0));
            lp.y = __float2half(v1 - __half2float(h1));
            size_t o = (size_t)row0 * DD + col;
            *(__half2*)(Oh + o) = hp;
            *(__half2*)(Ol + o) = lp;
        }
        {
            float v0 = oacc[nt][2] * inv1, v1 = oacc[nt][3] * inv1;
            __half h0 = __float2half(v0), h1 = __float2half(v1);
            __half2 hp; hp.x = h0; hp.y = h1;
            __half2 lp;
            lp.x = __float2half(v0 - __half2float(h0));
            lp.y = __float2half(v1 - __half2float(h1));
            size_t o = (size_t)(row0 + 8) * DD + col;
            *(__half2*)(Oh + o) = hp;
            *(__half2*)(Ol + o) = lp;
        }
    }
}

// ---------------- launch ----------------
extern "C" void kernel_launch(void* const* d_in, const int* in_sizes, int n_in,
                              void* d_out, int out_size)
{
    const float* x      = (const float*)d_in[0];
    const int*   mask   = (const int*)d_in[1];
    const float* ln1_g  = (const float*)d_in[2];
    const float* ln1_b  = (const float*)d_in[3];
    const float* wq     = (const float*)d_in[4];
    const float* wk     = (const float*)d_in[5];
    const float* wv     = (const float*)d_in[6];
    const float* wo     = (const float*)d_in[7];
    const float* bo     = (const float*)d_in[8];
    const float* ln2_g  = (const float*)d_in[9];
    const float* ln2_b  = (const float*)d_in[10];
    const float* w1     = (const float*)d_in[11];
    const float* b1     = (const float*)d_in[12];
    const float* w2     = (const float*)d_in[13];
    const float* b2     = (const float*)d_in[14];
    float* out = (float*)d_out;

    __half *lnh, *lnl, *qkvh, *qkvl, *atth, *attl, *hh, *hl;
    __half *wqkv, *wop, *w1p, *w2p;
    float *x1;
    cudaGetSymbolAddress((void**)&lnh,   g_lnh);   cudaGetSymbolAddress((void**)&lnl,   g_lnl);
    cudaGetSymbolAddress((void**)&qkvh,  g_qkvh);  cudaGetSymbolAddress((void**)&qkvl,  g_qkvl);
    cudaGetSymbolAddress((void**)&atth,  g_atth);  cudaGetSymbolAddress((void**)&attl,  g_attl);
    cudaGetSymbolAddress((void**)&x1,    g_x1);
    cudaGetSymbolAddress((void**)&hh,    g_hh);    cudaGetSymbolAddress((void**)&hl,    g_hl);
    cudaGetSymbolAddress((void**)&wqkv,  g_wqkv);
    cudaGetSymbolAddress((void**)&wop,   g_wo);
    cudaGetSymbolAddress((void**)&w1p,   g_w1);
    cudaGetSymbolAddress((void**)&w2p,   g_w2);

    cudaFuncSetAttribute(mma_gemm,  cudaFuncAttributeMaxDynamicSharedMemorySize, SMEM_GEMM);
    cudaFuncSetAttribute(flash_mma, cudaFuncAttributeMaxDynamicSharedMemorySize, SMEM_FLASH);

    // 0) weight transpose (fp16); q/k/v concatenated along N in wqkv
    dim3 tb(32, 8);
    wprep_kernel<<<dim3(DD/32, DD/32), tb>>>(wq, wqkv,                   DD, DD);
    wprep_kernel<<<dim3(DD/32, DD/32), tb>>>(wk, wqkv + (size_t)DD*DD,   DD, DD);
    wprep_kernel<<<dim3(DD/32, DD/32), tb>>>(wv, wqkv + (size_t)2*DD*DD, DD, DD);
    wprep_kernel<<<dim3(DD/32, DD/32), tb>>>(wo, wop, DD, DD);
    wprep_kernel<<<dim3(FF/32, DD/32), tb>>>(w1, w1p, DD, FF);
    wprep_kernel<<<dim3(DD/32, FF/32), tb>>>(w2, w2p, FF, DD);

    // 1) LN1 -> split
    ln_kernel<<<ROWS, 256>>>(x, ln1_g, ln1_b, lnh, lnl);

    // 2) fused QKV projection -> qkv split buffers [ROWS][3072]
    dim3 gQKV(QKD/128, ROWS/128);
    mma_gemm<<<gQKV, 512, SMEM_GEMM>>>(lnh, lnl, wqkv, nullptr, nullptr,
                                       nullptr, qkvh, qkvl, ROWS, QKD, DD, 0);

    // 3) attention (tensor cores, pipelined) -> split output
    dim3 gF(SS/128, HH, BB);
    flash_mma<<<gF, 256, SMEM_FLASH>>>(qkvh, qkvl, mask, atth, attl);

    // 4) output projection + bias + residual -> x1 (fp32)
    dim3 gO(DD/128, ROWS/128);
    mma_gemm<<<gO, 512, SMEM_GEMM>>>(atth, attl, wop, bo, x, x1, nullptr, nullptr, ROWS, DD, DD, 0);

    // 5) LN2 -> split
    ln_kernel<<<ROWS, 256>>>(x1, ln2_g, ln2_b, lnh, lnl);

    // 6) MLP up + bias + gelu -> split h
    dim3 gM1(FF/128, ROWS/128);
    mma_gemm<<<gM1, 512, SMEM_GEMM>>>(lnh, lnl, w1p, b1, nullptr, nullptr, hh, hl, ROWS, FF, DD, 1);

    // 7) MLP down + bias + residual -> out
    dim3 gM2(DD/128, ROWS/128);
    mma_gemm<<<gM2, 512, SMEM_GEMM>>>(hh, hl, w2p, b2, x1, out, nullptr, nullptr, ROWS, DD, FF, 0);
}

// round 16
// speedup vs baseline: 5.6414x; 1.5850x over previous
#include <cuda_runtime.h>
#include <cuda_fp16.h>
#include <math.h>
#include <stdint.h>

// Problem constants
#define BB 4
#define SS 2048
#define DD 1024
#define HH 16
#define HD 64
#define FF 4096
#define ROWS (BB*SS)          // 8192
#define QKD 3072              // fused qkv width

// ---------------- scratch (device globals; no allocation) ----------------
__device__ __half g_ln [(size_t)ROWS * DD];
__device__ __half g_qkv[(size_t)ROWS * QKD];
__device__ __half g_att[(size_t)ROWS * DD];
__device__ float  g_x1 [(size_t)ROWS * DD];
__device__ __half g_h  [(size_t)ROWS * FF];
// transposed weights (fp16): wt[N][K]
__device__ __half g_wqkv[(size_t)QKD*DD];
__device__ __half g_wo[(size_t)DD*DD];
__device__ __half g_w1[(size_t)DD*FF];
__device__ __half g_w2[(size_t)FF*DD];

// ---------------- helpers ----------------
__device__ __forceinline__ uint32_t smem_u32(const void* p) {
    uint32_t a;
    asm("{ .reg .u64 t; cvta.to.shared.u64 t, %1; cvt.u32.u64 %0, t; }" : "=r"(a) : "l"(p));
    return a;
}
__device__ __forceinline__ void ldm_x4(uint32_t& r0, uint32_t& r1, uint32_t& r2, uint32_t& r3, uint32_t a) {
    asm volatile("ldmatrix.sync.aligned.m8n8.x4.shared.b16 {%0,%1,%2,%3}, [%4];"
                 : "=r"(r0), "=r"(r1), "=r"(r2), "=r"(r3) : "r"(a));
}
__device__ __forceinline__ void ldm_x4_t(uint32_t& r0, uint32_t& r1, uint32_t& r2, uint32_t& r3, uint32_t a) {
    asm volatile("ldmatrix.sync.aligned.m8n8.x4.trans.shared.b16 {%0,%1,%2,%3}, [%4];"
                 : "=r"(r0), "=r"(r1), "=r"(r2), "=r"(r3) : "r"(a));
}
__device__ __forceinline__ void ldm_x2(uint32_t& r0, uint32_t& r1, uint32_t a) {
    asm volatile("ldmatrix.sync.aligned.m8n8.x2.shared.b16 {%0,%1}, [%2];"
                 : "=r"(r0), "=r"(r1) : "r"(a));
}
__device__ __forceinline__ void mma16816(float* c, const uint32_t* a, const uint32_t* b) {
    asm volatile("mma.sync.aligned.m16n8k16.row.col.f32.f16.f16.f32 "
                 "{%0,%1,%2,%3}, {%4,%5,%6,%7}, {%8,%9}, {%0,%1,%2,%3};"
                 : "+f"(c[0]), "+f"(c[1]), "+f"(c[2]), "+f"(c[3])
                 : "r"(a[0]), "r"(a[1]), "r"(a[2]), "r"(a[3]), "r"(b[0]), "r"(b[1]));
}
__device__ __forceinline__ uint32_t pack2h(float a, float b) {
    __half2 t = __floats2half2_rn(a, b);
    return *(uint32_t*)&t;
}
#define CP_ASYNC16(dst, src) asm volatile("cp.async.cg.shared.global [%0], [%1], 16;" :: "r"(dst), "l"(src))
#define CP_COMMIT()  asm volatile("cp.async.commit_group;")
#define CP_WAIT0()   asm volatile("cp.async.wait_group 0;")
#define CP_WAIT1()   asm volatile("cp.async.wait_group 1;")

// ---------------- LayerNorm -> fp16 ----------------
__global__ void ln_kernel(const float* __restrict__ x,
                          const float* __restrict__ g,
                          const float* __restrict__ b,
                          __half* __restrict__ oh)
{
    const int row = blockIdx.x;
    const float* xr = x + (size_t)row * DD;

    float s = 0.f, s2 = 0.f;
    for (int i = threadIdx.x; i < DD; i += blockDim.x) {
        float v = xr[i];
        s += v; s2 += v * v;
    }
    __shared__ float red[64];
    for (int o = 16; o; o >>= 1) {
        s  += __shfl_xor_sync(0xffffffffu, s,  o);
        s2 += __shfl_xor_sync(0xffffffffu, s2, o);
    }
    int wid = threadIdx.x >> 5, lid = threadIdx.x & 31;
    if (lid == 0) { red[wid] = s; red[wid + 32] = s2; }
    __syncthreads();
    if (wid == 0) {
        int nw = blockDim.x >> 5;
        s  = (lid < nw) ? red[lid] : 0.f;
        s2 = (lid < nw) ? red[lid + 32] : 0.f;
        for (int o = 16; o; o >>= 1) {
            s  += __shfl_xor_sync(0xffffffffu, s,  o);
            s2 += __shfl_xor_sync(0xffffffffu, s2, o);
        }
        if (lid == 0) { red[0] = s; red[1] = s2; }
    }
    __syncthreads();
    float mean = red[0] * (1.0f / DD);
    float var  = red[1] * (1.0f / DD) - mean * mean;
    float inv  = rsqrtf(var + 1e-5f);
    for (int i = threadIdx.x; i < DD; i += blockDim.x) {
        float v = (xr[i] - mean) * inv * g[i] + b[i];
        oh[(size_t)row * DD + i] = __float2half(v);
    }
}

// ---------------- weight transpose: w[K,N] -> th[N,K] fp16 ----------------
__global__ void wprep_kernel(const float* __restrict__ w,
                             __half* __restrict__ th, int K, int N)
{
    __shared__ float t[32][33];
    int nx0 = blockIdx.x * 32, ky0 = blockIdx.y * 32;
    int tx = threadIdx.x, ty = threadIdx.y;   // 32 x 8
    #pragma unroll
    for (int d = 0; d < 4; d++)
        t[ty + d * 8][tx] = w[(size_t)(ky0 + ty + d * 8) * N + nx0 + tx];
    __syncthreads();
    #pragma unroll
    for (int d = 0; d < 4; d++)
        th[(size_t)(nx0 + ty + d * 8) * K + ky0 + tx] = __float2half(t[tx][ty + d * 8]);
}

// ---------------- mma.sync fp16 GEMM, 512 threads -------------------------
// C[M,N] = A[M,K] @ B[N,K]^T, fp32 accum.
// CTA tile 128x128, BK=32, 512 threads (16 warps 4m x 4n, warp tile 32x32),
// 2-stage cp.async. Packed x4 ldmatrix for B.
#define LDT 40                    // smem row stride (32 + 8 pad) -> 80B
#define GARR (128*LDT*2)          // 10240 B per array
#define GSTG (2*GARR)             // 20480 B per stage (A, B)
#define SMEM_GEMM (2*GSTG)        // 40960 B

__global__ void __launch_bounds__(512, 1)
mma_gemm(const __half* __restrict__ A, const __half* __restrict__ B,
         const float* __restrict__ bias, const float* __restrict__ resid,
         float* __restrict__ Cf, __half* __restrict__ Ch,
         int M, int N, int K, int dogelu)
{
    extern __shared__ char gsm[];
    const uint32_t sb = smem_u32(gsm);

    const int tid = threadIdx.x, lane = tid & 31, wid = tid >> 5;
    const int wm = wid & 3, wn = wid >> 2;           // 4m x 4n warps, tile 32x32
    const int bm = blockIdx.y * 128, bn = blockIdx.x * 128;

    float acc[2][4][4];
    #pragma unroll
    for (int i = 0; i < 2; i++)
        #pragma unroll
        for (int j = 0; j < 4; j++)
            #pragma unroll
            for (int r = 0; r < 4; r++) acc[i][j][r] = 0.f;

    const int l_r = tid >> 2, l_c8 = (tid & 3) * 8;
    const uint32_t a_off = (uint32_t)((lane & 15) * LDT + (lane >> 4) * 8) * 2;
    // B packed x4: lanes 0-7:(n0,k0) 8-15:(n0,k1) 16-23:(n0+8,k0) 24-31:(n0+8,k1)
    const uint32_t bp_off = (uint32_t)(((lane & 7) + ((lane >> 4) & 1) * 8) * LDT
                                       + ((lane >> 3) & 1) * 8) * 2;

    const int T = K >> 5;

    // prologue: stages 0, 1
    #pragma unroll
    for (int p = 0; p < 2; p++) {
        const int kn = p << 5;
        const uint32_t st = (uint32_t)p * GSTG;
        uint32_t so = st + (uint32_t)(l_r * LDT + l_c8) * 2;
        size_t ga = (size_t)(bm + l_r) * K + kn + l_c8;
        size_t gb = (size_t)(bn + l_r) * K + kn + l_c8;
        CP_ASYNC16(sb + 0*GARR + so, A + ga);
        CP_ASYNC16(sb + 1*GARR + so, B + gb);
        CP_COMMIT();
    }

    for (int t = 0; t < T; t++) {
        if (t + 1 < T) { CP_WAIT1(); } else { CP_WAIT0(); }
        __syncthreads();

        const uint32_t st = (uint32_t)(t & 1) * GSTG;
        const uint32_t sA_b = sb + st, sB_b = sb + st + GARR;

        #pragma unroll
        for (int ks = 0; ks < 2; ks++) {
            const uint32_t kso = ks * 16 * 2;
            uint32_t ah[2][4], bf[4][2];
            #pragma unroll
            for (int mt = 0; mt < 2; mt++) {
                uint32_t base = (uint32_t)((wm * 32 + mt * 16) * LDT) * 2 + kso + a_off;
                ldm_x4(ah[mt][0], ah[mt][1], ah[mt][2], ah[mt][3], sA_b + base);
            }
            #pragma unroll
            for (int p = 0; p < 2; p++) {    // nt pair (2p, 2p+1)
                uint32_t base = (uint32_t)((wn * 32 + p * 16) * LDT) * 2 + kso + bp_off;
                ldm_x4(bf[2*p][0], bf[2*p][1], bf[2*p+1][0], bf[2*p+1][1], sB_b + base);
            }
            #pragma unroll
            for (int mt = 0; mt < 2; mt++)
                #pragma unroll
                for (int nt = 0; nt < 4; nt++)
                    mma16816(acc[mt][nt], ah[mt], bf[nt]);
        }
        __syncthreads();

        if (t + 2 < T) {
            const int kn = (t + 2) << 5;
            const uint32_t sti = (uint32_t)(t & 1) * GSTG;
            uint32_t so = sti + (uint32_t)(l_r * LDT + l_c8) * 2;
            size_t ga = (size_t)(bm + l_r) * K + kn + l_c8;
            size_t gb = (size_t)(bn + l_r) * K + kn + l_c8;
            CP_ASYNC16(sb + 0*GARR + so, A + ga);
            CP_ASYNC16(sb + 1*GARR + so, B + gb);
            CP_COMMIT();
        }
    }

    // epilogue
    const int mrow = bm + wm * 32 + (lane >> 2);
    const int ncol = bn + wn * 32 + (lane & 3) * 2;
    #pragma unroll
    for (int mt = 0; mt < 2; mt++) {
        #pragma unroll
        for (int half = 0; half < 2; half++) {
            int row = mrow + mt * 16 + half * 8;
            #pragma unroll
            for (int nt = 0; nt < 4; nt++) {
                int col = ncol + nt * 8;
                float v0 = acc[mt][nt][half * 2 + 0];
                float v1 = acc[mt][nt][half * 2 + 1];
                if (bias) { v0 += __ldg(bias + col); v1 += __ldg(bias + col + 1); }
                if (dogelu) {
                    v0 = 0.5f * v0 * (1.0f + erff(v0 * 0.70710678118654752f));
                    v1 = 0.5f * v1 * (1.0f + erff(v1 * 0.70710678118654752f));
                }
                size_t o = (size_t)row * N + col;
                if (resid) { v0 += resid[o]; v1 += resid[o + 1]; }
                if (Cf) { *(float2*)(Cf + o) = make_float2(v0, v1); }
                if (Ch) {
                    __half2 hp; hp.x = __float2half(v0); hp.y = __float2half(v1);
                    *(__half2*)(Ch + o) = hp;
                }
            }
        }
    }
}

// ---------------- Flash attention, fp16 mma, pipelined --------------------
// CTA: 256 threads (8 warps), 128 q-rows x one head, 64-key tiles.
// Single fp16 operands throughout, fp32 accumulation + softmax.
#define LDF 72
#define FQ  0
#define FKV 18432                 // 2 arrays x 9216 per stage (K, V)
#define KVSTG 18432
#define FMK (FKV + 2*KVSTG)       // 55296; 2 x 32768
#define MKSTG 32768
#define SMEM_FLASH (FMK + 2*MKSTG)   // 120832

__global__ void __launch_bounds__(256, 1)
flash_mma(const __half* __restrict__ qkv,
          const int* __restrict__ mask,
          __half* __restrict__ Oh)
{
    extern __shared__ char fsm[];
    const uint32_t sb = smem_u32(fsm);

    const int b = blockIdx.z, h = blockIdx.y;
    const int q0 = blockIdx.x * 128;
    const int tid = threadIdx.x, lane = tid & 31, w = tid >> 5;

    // ---- prologue: Q tile (group 0), KV+mask tile 0 (group 1) ----
    #pragma unroll
    for (int j = 0; j < 4; j++) {
        int e = tid + j * 256;           // 1024 chunks
        int r = e >> 3, c8 = (e & 7) * 8;
        size_t gq = (size_t)(b * SS + q0 + r) * QKD + h * HD + c8;
        CP_ASYNC16(sb + FQ + (uint32_t)(r * LDF + c8) * 2, qkv + gq);
    }
    CP_COMMIT();
    {
        const uint32_t kvb = sb + FKV, mkb = sb + FMK;
        #pragma unroll
        for (int j = 0; j < 2; j++) {
            int e = tid + j * 256;       // 512 chunks
            int r = e >> 3, c8 = (e & 7) * 8;
            size_t gk = (size_t)(b * SS + r) * QKD + DD + h * HD + c8;
            uint32_t so = (uint32_t)(r * LDF + c8) * 2;
            CP_ASYNC16(kvb + 0*9216 + so, qkv + gk);
            CP_ASYNC16(kvb + 1*9216 + so, qkv + gk + DD);
        }
        #pragma unroll
        for (int j = 0; j < 8; j++) {
            int e = tid + j * 256;       // 2048 int4
            int r = e >> 4, c4 = (e & 15) * 4;
            CP_ASYNC16(mkb + (uint32_t)(r * 64 + c4) * 4,
                       mask + (size_t)(b * SS + q0 + r) * SS + c4);
        }
        CP_COMMIT();
    }

    CP_WAIT1();           // Q ready (tile0 may still be in flight)
    __syncthreads();

    const uint32_t a_off = (uint32_t)((lane & 15) * LDF + (lane >> 4) * 8) * 2;
    const uint32_t b_off = (uint32_t)((lane & 7) * LDF + ((lane >> 3) & 1) * 8) * 2;

    uint32_t qf[4][4];
    #pragma unroll
    for (int ks = 0; ks < 4; ks++) {
        uint32_t base = (uint32_t)(w * 16 * LDF) * 2 + (uint32_t)(ks * 16) * 2 + a_off;
        ldm_x4(qf[ks][0], qf[ks][1], qf[ks][2], qf[ks][3], sb + FQ + base);
    }

    float oacc[8][4];
    #pragma unroll
    for (int i = 0; i < 8; i++)
        #pragma unroll
        for (int j = 0; j < 4; j++) oacc[i][j] = 0.f;
    float m0 = -INFINITY, m1 = -INFINITY, l0 = 0.f, l1 = 0.f;
    int any0 = 0, any1 = 0;
    const int lr0 = lane >> 2;

    const int T = SS / 64;
    for (int t = 0; t < T; t++) {
        // prefetch tile t+1 into stage (t+1)&1
        if (t + 1 < T) {
            const int t0n = (t + 1) * 64;
            const uint32_t kvb = sb + FKV + (uint32_t)((t + 1) & 1) * KVSTG;
            const uint32_t mkb = sb + FMK + (uint32_t)((t + 1) & 1) * MKSTG;
            #pragma unroll
            for (int j = 0; j < 2; j++) {
                int e = tid + j * 256;
                int r = e >> 3, c8 = (e & 7) * 8;
                size_t gk = (size_t)(b * SS + t0n + r) * QKD + DD + h * HD + c8;
                uint32_t so = (uint32_t)(r * LDF + c8) * 2;
                CP_ASYNC16(kvb + 0*9216 + so, qkv + gk);
                CP_ASYNC16(kvb + 1*9216 + so, qkv + gk + DD);
            }
            #pragma unroll
            for (int j = 0; j < 8; j++) {
                int e = tid + j * 256;
                int r = e >> 4, c4 = (e & 15) * 4;
                CP_ASYNC16(mkb + (uint32_t)(r * 64 + c4) * 4,
                           mask + (size_t)(b * SS + q0 + r) * SS + t0n + c4);
            }
            CP_COMMIT();
            CP_WAIT1();
        } else {
            CP_WAIT0();
        }
        __syncthreads();

        const uint32_t kvb = sb + FKV + (uint32_t)(t & 1) * KVSTG;
        const uint32_t sk_b = kvb, sv_b = kvb + 9216;
        const int* smsk = (const int*)(fsm + FMK + (size_t)(t & 1) * MKSTG);

        // scores S[16 q][64 k] per warp
        float sc[8][4];
        #pragma unroll
        for (int i = 0; i < 8; i++)
            #pragma unroll
            for (int j = 0; j < 4; j++) sc[i][j] = 0.f;

        #pragma unroll
        for (int ks = 0; ks < 4; ks++) {
            uint32_t kf[8][2];
            #pragma unroll
            for (int nt = 0; nt < 8; nt++) {
                uint32_t base = (uint32_t)(nt * 8 * LDF) * 2 + (uint32_t)(ks * 16) * 2 + b_off;
                ldm_x2(kf[nt][0], kf[nt][1], sk_b + base);
            }
            #pragma unroll
            for (int nt = 0; nt < 8; nt++)
                mma16816(sc[nt], qf[ks], kf[nt]);
        }

        // mask + scale + row max
        float tmax0 = -INFINITY, tmax1 = -INFINITY;
        #pragma unroll
        for (int nt = 0; nt < 8; nt++) {
            int c = nt * 8 + (lane & 3) * 2;
            int2 mv0 = *(const int2*)&smsk[(w * 16 + lr0) * 64 + c];
            int2 mv1 = *(const int2*)&smsk[(w * 16 + lr0 + 8) * 64 + c];
            any0 |= mv0.x | mv0.y;
            any1 |= mv1.x | mv1.y;
            sc[nt][0] = mv0.x ? sc[nt][0] * 0.125f : -1e30f;
            sc[nt][1] = mv0.y ? sc[nt][1] * 0.125f : -1e30f;
            sc[nt][2] = mv1.x ? sc[nt][2] * 0.125f : -1e30f;
            sc[nt][3] = mv1.y ? sc[nt][3] * 0.125f : -1e30f;
            tmax0 = fmaxf(tmax0, fmaxf(sc[nt][0], sc[nt][1]));
            tmax1 = fmaxf(tmax1, fmaxf(sc[nt][2], sc[nt][3]));
        }
        tmax0 = fmaxf(tmax0, __shfl_xor_sync(0xffffffffu, tmax0, 1));
        tmax0 = fmaxf(tmax0, __shfl_xor_sync(0xffffffffu, tmax0, 2));
        tmax1 = fmaxf(tmax1, __shfl_xor_sync(0xffffffffu, tmax1, 1));
        tmax1 = fmaxf(tmax1, __shfl_xor_sync(0xffffffffu, tmax1, 2));

        float mn0 = fmaxf(m0, tmax0), mn1 = fmaxf(m1, tmax1);
        float corr0 = __expf(m0 - mn0), corr1 = __expf(m1 - mn1);
        m0 = mn0; m1 = mn1;

        float ps0 = 0.f, ps1 = 0.f;
        #pragma unroll
        for (int nt = 0; nt < 8; nt++) {
            sc[nt][0] = __expf(sc[nt][0] - mn0);
            sc[nt][1] = __expf(sc[nt][1] - mn0);
            sc[nt][2] = __expf(sc[nt][2] - mn1);
            sc[nt][3] = __expf(sc[nt][3] - mn1);
            ps0 += sc[nt][0] + sc[nt][1];
            ps1 += sc[nt][2] + sc[nt][3];
        }
        ps0 += __shfl_xor_sync(0xffffffffu, ps0, 1);
        ps0 += __shfl_xor_sync(0xffffffffu, ps0, 2);
        ps1 += __shfl_xor_sync(0xffffffffu, ps1, 1);
        ps1 += __shfl_xor_sync(0xffffffffu, ps1, 2);
        l0 = l0 * corr0 + ps0;
        l1 = l1 * corr1 + ps1;

        #pragma unroll
        for (int d = 0; d < 8; d++) {
            oacc[d][0] *= corr0; oacc[d][1] *= corr0;
            oacc[d][2] *= corr1; oacc[d][3] *= corr1;
        }

        // PV (single-term)
        #pragma unroll
        for (int kc = 0; kc < 4; kc++) {
            uint32_t pa[4];
            pa[0] = pack2h(sc[2*kc][0],   sc[2*kc][1]);
            pa[1] = pack2h(sc[2*kc][2],   sc[2*kc][3]);
            pa[2] = pack2h(sc[2*kc+1][0], sc[2*kc+1][1]);
            pa[3] = pack2h(sc[2*kc+1][2], sc[2*kc+1][3]);
            #pragma unroll
            for (int nt2 = 0; nt2 < 4; nt2++) {
                int key = kc * 16 + ((lane >> 3) & 1) * 8 + (lane & 7);
                int dimb = nt2 * 16 + (lane >> 4) * 8;
                uint32_t ad = (uint32_t)(key * LDF + dimb) * 2;
                uint32_t v0, v1, v2, v3;
                ldm_x4_t(v0, v1, v2, v3, sv_b + ad);
                uint32_t b0[2] = {v0, v1}, b1[2] = {v2, v3};
                mma16816(oacc[nt2*2],     pa, b0);
                mma16816(oacc[nt2*2 + 1], pa, b1);
            }
        }
        __syncthreads();
    }

    // finalize
    any0 |= __shfl_xor_sync(0xffffffffu, any0, 1);
    any0 |= __shfl_xor_sync(0xffffffffu, any0, 2);
    any1 |= __shfl_xor_sync(0xffffffffu, any1, 1);
    any1 |= __shfl_xor_sync(0xffffffffu, any1, 2);
    float inv0 = (any0 && l0 > 0.f) ? (1.0f / l0) : 0.0f;
    float inv1 = (any1 && l1 > 0.f) ? (1.0f / l1) : 0.0f;

    const int row0 = b * SS + q0 + w * 16 + lr0;
    #pragma unroll
    for (int nt = 0; nt < 8; nt++) {
        int col = h * HD + nt * 8 + (lane & 3) * 2;
        {
            __half2 hp; hp.x = __float2half(oacc[nt][0] * inv0);
            hp.y = __float2half(oacc[nt][1] * inv0);
            *(__half2*)(Oh + (size_t)row0 * DD + col) = hp;
        }
        {
            __half2 hp; hp.x = __float2half(oacc[nt][2] * inv1);
            hp.y = __float2half(oacc[nt][3] * inv1);
            *(__half2*)(Oh + (size_t)(row0 + 8) * DD + col) = hp;
        }
    }
}

// ---------------- launch ----------------
extern "C" void kernel_launch(void* const* d_in, const int* in_sizes, int n_in,
                              void* d_out, int out_size)
{
    const float* x      = (const float*)d_in[0];
    const int*   mask   = (const int*)d_in[1];
    const float* ln1_g  = (const float*)d_in[2];
    const float* ln1_b  = (const float*)d_in[3];
    const float* wq     = (const float*)d_in[4];
    const float* wk     = (const float*)d_in[5];
    const float* wv     = (const float*)d_in[6];
    const float* wo     = (const float*)d_in[7];
    const float* bo     = (const float*)d_in[8];
    const float* ln2_g  = (const float*)d_in[9];
    const float* ln2_b  = (const float*)d_in[10];
    const float* w1     = (const float*)d_in[11];
    const float* b1     = (const float*)d_in[12];
    const float* w2     = (const float*)d_in[13];
    const float* b2     = (const float*)d_in[14];
    float* out = (float*)d_out;

    __half *ln, *qkv, *att, *hbuf;
    __half *wqkv, *wop, *w1p, *w2p;
    float *x1;
    cudaGetSymbolAddress((void**)&ln,    g_ln);
    cudaGetSymbolAddress((void**)&qkv,   g_qkv);
    cudaGetSymbolAddress((void**)&att,   g_att);
    cudaGetSymbolAddress((void**)&x1,    g_x1);
    cudaGetSymbolAddress((void**)&hbuf,  g_h);
    cudaGetSymbolAddress((void**)&wqkv,  g_wqkv);
    cudaGetSymbolAddress((void**)&wop,   g_wo);
    cudaGetSymbolAddress((void**)&w1p,   g_w1);
    cudaGetSymbolAddress((void**)&w2p,   g_w2);

    cudaFuncSetAttribute(mma_gemm,  cudaFuncAttributeMaxDynamicSharedMemorySize, SMEM_GEMM);
    cudaFuncSetAttribute(flash_mma, cudaFuncAttributeMaxDynamicSharedMemorySize, SMEM_FLASH);

    // 0) weight transpose (fp16); q/k/v concatenated along N in wqkv
    dim3 tb(32, 8);
    wprep_kernel<<<dim3(DD/32, DD/32), tb>>>(wq, wqkv,                   DD, DD);
    wprep_kernel<<<dim3(DD/32, DD/32), tb>>>(wk, wqkv + (size_t)DD*DD,   DD, DD);
    wprep_kernel<<<dim3(DD/32, DD/32), tb>>>(wv, wqkv + (size_t)2*DD*DD, DD, DD);
    wprep_kernel<<<dim3(DD/32, DD/32), tb>>>(wo, wop, DD, DD);
    wprep_kernel<<<dim3(FF/32, DD/32), tb>>>(w1, w1p, DD, FF);
    wprep_kernel<<<dim3(DD/32, FF/32), tb>>>(w2, w2p, FF, DD);

    // 1) LN1 -> fp16
    ln_kernel<<<ROWS, 256>>>(x, ln1_g, ln1_b, ln);

    // 2) fused QKV projection -> qkv buffer [ROWS][3072]
    dim3 gQKV(QKD/128, ROWS/128);
    mma_gemm<<<gQKV, 512, SMEM_GEMM>>>(ln, wqkv, nullptr, nullptr,
                                       nullptr, qkv, ROWS, QKD, DD, 0);

    // 3) attention (tensor cores, pipelined) -> fp16 output
    dim3 gF(SS/128, HH, BB);
    flash_mma<<<gF, 256, SMEM_FLASH>>>(qkv, mask, att);

    // 4) output projection + bias + residual -> x1 (fp32)
    dim3 gO(DD/128, ROWS/128);
    mma_gemm<<<gO, 512, SMEM_GEMM>>>(att, wop, bo, x, x1, nullptr, ROWS, DD, DD, 0);

    // 5) LN2 -> fp16
    ln_kernel<<<ROWS, 256>>>(x1, ln2_g, ln2_b, ln);

    // 6) MLP up + bias + gelu -> fp16 h
    dim3 gM1(FF/128, ROWS/128);
    mma_gemm<<<gM1, 512, SMEM_GEMM>>>(ln, w1p, b1, nullptr, nullptr, hbuf, ROWS, FF, DD, 1);

    // 7) MLP down + bias + residual -> out
    dim3 gM2(DD/128, ROWS/128);
    mma_gemm<<<gM2, 512, SMEM_GEMM>>>(hbuf, w2p, b2, x1, out, nullptr, ROWS, DD, FF, 0);
}